// round 4
// baseline (speedup 1.0000x reference)
#include <cuda_runtime.h>

// ---------------------------------------------------------------------------
// GNN: L x { agg = scatter_add(h[src]*ew, dst); h = PReLU(LN(agg@Wrel + h@Wroot + b)) }
// then logits = LN(relu(h@W1+b1)) @ W2 + b2
// R4: CSR gather fused INTO the gemm kernel (agg never hits global memory);
//     gather L2 latency hidden under other warps' FFMA2 issue.
// ---------------------------------------------------------------------------

#define MAXN 100000
#define MAXE 1600000
#define DD   128
typedef unsigned long long U64;

__device__ float g_buf0[MAXN * DD];
__device__ float g_buf1[MAXN * DD];
__device__ int   g_cnt [MAXN];        // histogram, then reused as cursor
__device__ int   g_off [MAXN + 1];
__device__ int   g_bsum[128];
__device__ int   g_esrc[MAXE];
__device__ float g_ewt [MAXE];

// ---- packed f32x2 helpers ----
__device__ __forceinline__ U64 pk2(float lo, float hi) {
    U64 r; asm("mov.b64 %0,{%1,%2};" : "=l"(r) : "f"(lo), "f"(hi)); return r;
}
__device__ __forceinline__ void upk2(U64 v, float& lo, float& hi) {
    asm("mov.b64 {%0,%1},%2;" : "=f"(lo), "=f"(hi) : "l"(v));
}
__device__ __forceinline__ U64 f2(U64 a, U64 b, U64 c) {
    asm("fma.rn.f32x2 %0,%1,%2,%0;" : "+l"(c) : "l"(a), "l"(b)); return c;
}
__device__ __forceinline__ U64 add2(U64 a, U64 b) {
    U64 r; asm("add.rn.f32x2 %0,%1,%2;" : "=l"(r) : "l"(a), "l"(b)); return r;
}
__device__ __forceinline__ U64 mul2(U64 a, U64 b) {
    U64 r; asm("mul.rn.f32x2 %0,%1,%2;" : "=l"(r) : "l"(a), "l"(b)); return r;
}
__device__ __forceinline__ U64 shfl64(U64 v, int o) {
    return (U64)__shfl_xor_sync(0xffffffffu, (long long)v, o);
}

// ======================= CSR build (once per call) =========================
__global__ void hist_kernel(const int* __restrict__ ei, int* __restrict__ cnt, int E) {
    int e = blockIdx.x * blockDim.x + threadIdx.x;
    if (e < E) atomicAdd(cnt + __ldg(ei + E + e), 1);
}

__global__ void scan1_kernel(const int* __restrict__ cnt, int* __restrict__ off,
                             int* __restrict__ bsum, int N) {
    __shared__ int s[1024];
    int tid = threadIdx.x;
    int i = blockIdx.x * 1024 + tid;
    int v = (i < N) ? cnt[i] : 0;
    s[tid] = v; __syncthreads();
    #pragma unroll
    for (int d = 1; d < 1024; d <<= 1) {
        int t = (tid >= d) ? s[tid - d] : 0;
        __syncthreads();
        s[tid] += t;
        __syncthreads();
    }
    if (i < N) off[i] = s[tid] - v;
    if (tid == 1023) bsum[blockIdx.x] = s[1023];
}

__global__ void scan2_kernel(int* __restrict__ bsum, int* __restrict__ off,
                             int NB, int N) {
    __shared__ int s[128];
    int tid = threadIdx.x;
    int v = (tid < NB) ? bsum[tid] : 0;
    s[tid] = v; __syncthreads();
    #pragma unroll
    for (int d = 1; d < 128; d <<= 1) {
        int t = (tid >= d) ? s[tid - d] : 0;
        __syncthreads();
        s[tid] += t;
        __syncthreads();
    }
    if (tid < NB) bsum[tid] = s[tid] - v;
    if (tid == 127) off[N] = s[127];
}

__global__ void scan3_kernel(int* __restrict__ off, const int* __restrict__ bsum, int N) {
    int i = blockIdx.x * blockDim.x + threadIdx.x;
    if (i < N) off[i] += bsum[i >> 10];
}

__global__ void place_kernel(const int* __restrict__ ei, const float* __restrict__ ew,
                             const int* __restrict__ off, int* __restrict__ cursor,
                             int* __restrict__ esrc, float* __restrict__ ewt, int E) {
    int e = blockIdx.x * blockDim.x + threadIdx.x;
    if (e >= E) return;
    int src = __ldg(ei + e);
    int dst = __ldg(ei + E + e);
    int pos = off[dst] + atomicAdd(cursor + dst, 1);
    esrc[pos] = src;
    ewt[pos]  = __ldg(ew + e);
}

// ==== Fused layer: CSR gather + dual-GEMM + bias + LN + PReLU ==============
// 384 threads (12 warps); each warp: gather 8 agg rows from CSR into f32x2
// staging, load 8 h rows, then 8-row FFMA2 GEMM + LN + PReLU epilogue.
__global__ __launch_bounds__(384, 1)
void layer_kernel(const float* __restrict__ hin,
                  const int*   __restrict__ off,
                  const int*   __restrict__ esrc,
                  const float* __restrict__ ewt,
                  const float* __restrict__ Wrel,
                  const float* __restrict__ Wroot,
                  const float* __restrict__ bias,
                  const float* __restrict__ lng,
                  const float* __restrict__ lnb,
                  const float* __restrict__ alpha,
                  float*       __restrict__ hout,
                  int N) {
    extern __shared__ float smem[];
    float4* sWr4 = reinterpret_cast<float4*>(smem);             // 64 KB
    float4* sWo4 = reinterpret_cast<float4*>(smem + 16384);     // 64 KB
    U64*    sP   = reinterpret_cast<U64*>(smem + 32768);        // 96 KB staging

    int tid = threadIdx.x, lane = tid & 31, warp = tid >> 5;

    const float4* Wr4 = reinterpret_cast<const float4*>(Wrel);
    const float4* Wo4 = reinterpret_cast<const float4*>(Wroot);
    for (int i = tid; i < 4096; i += 384) { sWr4[i] = Wr4[i]; sWo4[i] = Wo4[i]; }
    __syncthreads();

    float  al  = __ldg(alpha);
    float4 biv = *reinterpret_cast<const float4*>(bias + lane * 4);
    float4 gg  = *reinterpret_cast<const float4*>(lng  + lane * 4);
    float4 bb  = *reinterpret_cast<const float4*>(lnb  + lane * 4);
    float gA[4] = {gg.x, gg.y, gg.z, gg.w};
    float bA[4] = {bb.x, bb.y, bb.z, bb.w};
    U64 bp[4] = {pk2(biv.x, biv.x), pk2(biv.y, biv.y),
                 pk2(biv.z, biv.z), pk2(biv.w, biv.w)};
    const U64 NEG1   = pk2(-1.f, -1.f);
    const U64 INV128 = pk2(0.0078125f, 0.0078125f);

    U64* sw = sP + warp * 1024;   // 4 pairs x 2 mats x 128 u64
    int gw = blockIdx.x * 12 + warp;
    int stride = gridDim.x * 12 * 8;

    for (int base = gw * 8; base < N; base += stride) {
        __syncwarp();
        // -------- gather agg rows (CSR) + load h rows; stage as f32x2 pairs --
        #pragma unroll
        for (int p = 0; p < 4; p++) {
            int r0 = base + 2 * p, r1 = r0 + 1;
            float4 a0 = {0,0,0,0}, a1 = {0,0,0,0}, h0 = {0,0,0,0}, h1 = {0,0,0,0};
            #pragma unroll
            for (int half = 0; half < 2; half++) {
                int r = half ? r1 : r0;
                if (r >= N) break;
                int beg = __ldg(off + r), end = __ldg(off + r + 1);
                float4 acc = {0.f, 0.f, 0.f, 0.f};
                int e = beg;
                for (; e + 1 < end; e += 2) {
                    int   s0 = __ldg(esrc + e),  s1 = __ldg(esrc + e + 1);
                    float w0 = __ldg(ewt + e),   w1 = __ldg(ewt + e + 1);
                    float4 v0 = *reinterpret_cast<const float4*>(hin + (size_t)s0 * DD + lane * 4);
                    float4 v1 = *reinterpret_cast<const float4*>(hin + (size_t)s1 * DD + lane * 4);
                    acc.x = fmaf(w0, v0.x, fmaf(w1, v1.x, acc.x));
                    acc.y = fmaf(w0, v0.y, fmaf(w1, v1.y, acc.y));
                    acc.z = fmaf(w0, v0.z, fmaf(w1, v1.z, acc.z));
                    acc.w = fmaf(w0, v0.w, fmaf(w1, v1.w, acc.w));
                }
                if (e < end) {
                    int   s0 = __ldg(esrc + e);
                    float w0 = __ldg(ewt + e);
                    float4 v0 = *reinterpret_cast<const float4*>(hin + (size_t)s0 * DD + lane * 4);
                    acc.x = fmaf(w0, v0.x, acc.x);
                    acc.y = fmaf(w0, v0.y, acc.y);
                    acc.z = fmaf(w0, v0.z, acc.z);
                    acc.w = fmaf(w0, v0.w, acc.w);
                }
                float4 hv = *reinterpret_cast<const float4*>(hin + (size_t)r * DD + lane * 4);
                if (half) { a1 = acc; h1 = hv; } else { a0 = acc; h0 = hv; }
            }
            float2* da = reinterpret_cast<float2*>(sw + (2 * p) * 128);
            float2* dh = reinterpret_cast<float2*>(sw + (2 * p + 1) * 128);
            da[lane * 4 + 0] = make_float2(a0.x, a1.x);
            da[lane * 4 + 1] = make_float2(a0.y, a1.y);
            da[lane * 4 + 2] = make_float2(a0.z, a1.z);
            da[lane * 4 + 3] = make_float2(a0.w, a1.w);
            dh[lane * 4 + 0] = make_float2(h0.x, h1.x);
            dh[lane * 4 + 1] = make_float2(h0.y, h1.y);
            dh[lane * 4 + 2] = make_float2(h0.z, h1.z);
            dh[lane * 4 + 3] = make_float2(h0.w, h1.w);
        }
        __syncwarp();

        // -------- main K loop --------
        U64 acc[4][4];
        #pragma unroll
        for (int p = 0; p < 4; p++)
            #pragma unroll
            for (int c = 0; c < 4; c++) acc[p][c] = bp[c];

        #pragma unroll 4
        for (int k = 0; k < 128; k += 2) {
            float4 wr0 = sWr4[k * 32 + lane],      wr1 = sWr4[k * 32 + 32 + lane];
            float4 wo0 = sWo4[k * 32 + lane],      wo1 = sWo4[k * 32 + 32 + lane];
            U64 wr0p[4] = {pk2(wr0.x,wr0.x), pk2(wr0.y,wr0.y), pk2(wr0.z,wr0.z), pk2(wr0.w,wr0.w)};
            U64 wr1p[4] = {pk2(wr1.x,wr1.x), pk2(wr1.y,wr1.y), pk2(wr1.z,wr1.z), pk2(wr1.w,wr1.w)};
            U64 wo0p[4] = {pk2(wo0.x,wo0.x), pk2(wo0.y,wo0.y), pk2(wo0.z,wo0.z), pk2(wo0.w,wo0.w)};
            U64 wo1p[4] = {pk2(wo1.x,wo1.x), pk2(wo1.y,wo1.y), pk2(wo1.z,wo1.z), pk2(wo1.w,wo1.w)};
            #pragma unroll
            for (int p = 0; p < 4; p++) {
                ulonglong2 ap = *reinterpret_cast<const ulonglong2*>(sw + (2 * p) * 128 + k);
                ulonglong2 hp = *reinterpret_cast<const ulonglong2*>(sw + (2 * p + 1) * 128 + k);
                #pragma unroll
                for (int c = 0; c < 4; c++) {
                    acc[p][c] = f2(ap.x, wr0p[c], acc[p][c]);
                    acc[p][c] = f2(hp.x, wo0p[c], acc[p][c]);
                    acc[p][c] = f2(ap.y, wr1p[c], acc[p][c]);
                    acc[p][c] = f2(hp.y, wo1p[c], acc[p][c]);
                }
            }
        }

        // -------- epilogue: LayerNorm + PReLU --------
        #pragma unroll
        for (int p = 0; p < 4; p++) {
            U64 s = add2(add2(acc[p][0], acc[p][1]), add2(acc[p][2], acc[p][3]));
            #pragma unroll
            for (int o = 16; o; o >>= 1) s = add2(s, shfl64(s, o));
            U64 mu = mul2(s, INV128);
            U64 d[4];
            #pragma unroll
            for (int c = 0; c < 4; c++) d[c] = f2(mu, NEG1, acc[p][c]);
            U64 q = add2(add2(mul2(d[0], d[0]), mul2(d[1], d[1])),
                         add2(mul2(d[2], d[2]), mul2(d[3], d[3])));
            #pragma unroll
            for (int o = 16; o; o >>= 1) q = add2(q, shfl64(q, o));
            float ql, qh; upk2(q, ql, qh);
            float rl = rsqrtf(ql * 0.0078125f + 1e-5f);
            float rh = rsqrtf(qh * 0.0078125f + 1e-5f);

            int r0 = base + 2 * p, r1 = r0 + 1;
            float y0[4], y1[4];
            #pragma unroll
            for (int c = 0; c < 4; c++) {
                float dl, dh2; upk2(d[c], dl, dh2);
                float v0 = dl * rl * gA[c] + bA[c];
                float v1 = dh2 * rh * gA[c] + bA[c];
                y0[c] = v0 >= 0.f ? v0 : al * v0;
                y1[c] = v1 >= 0.f ? v1 : al * v1;
            }
            if (r0 < N)
                *reinterpret_cast<float4*>(hout + (size_t)r0 * DD + lane * 4) =
                    make_float4(y0[0], y0[1], y0[2], y0[3]);
            if (r1 < N)
                *reinterpret_cast<float4*>(hout + (size_t)r1 * DD + lane * 4) =
                    make_float4(y1[0], y1[1], y1[2], y1[3]);
        }
    }
}

// ======================= Classifier ========================================
__global__ __launch_bounds__(256, 2)
void classifier_kernel(const float* __restrict__ hin,
                       const float* __restrict__ W1,
                       const float* __restrict__ b1,
                       const float* __restrict__ lng,
                       const float* __restrict__ lnb,
                       const float* __restrict__ W2,
                       const float* __restrict__ b2,
                       float*       __restrict__ out,
                       int N) {
    extern __shared__ float smem[];
    float4* sW4 = reinterpret_cast<float4*>(smem);          // 64 KB
    U64*    sP  = reinterpret_cast<U64*>(smem + 16384);     // 32 KB staging

    int tid = threadIdx.x, lane = tid & 31, warp = tid >> 5;

    const float4* W14 = reinterpret_cast<const float4*>(W1);
    #pragma unroll
    for (int i = tid; i < 4096; i += 256) sW4[i] = W14[i];
    __syncthreads();

    float4 b1v = *reinterpret_cast<const float4*>(b1  + lane * 4);
    float4 gg  = *reinterpret_cast<const float4*>(lng + lane * 4);
    float4 bb  = *reinterpret_cast<const float4*>(lnb + lane * 4);
    float gA[4] = {gg.x, gg.y, gg.z, gg.w};
    float bA[4] = {bb.x, bb.y, bb.z, bb.w};
    U64 bp[4] = {pk2(b1v.x, b1v.x), pk2(b1v.y, b1v.y),
                 pk2(b1v.z, b1v.z), pk2(b1v.w, b1v.w)};
    const U64 NEG1   = pk2(-1.f, -1.f);
    const U64 INV128 = pk2(0.0078125f, 0.0078125f);

    float w2c0[4], w2c1[4];
    #pragma unroll
    for (int c = 0; c < 4; c++) {
        w2c0[c] = __ldg(W2 + (lane * 4 + c) * 2 + 0);
        w2c1[c] = __ldg(W2 + (lane * 4 + c) * 2 + 1);
    }
    float b20 = __ldg(b2 + 0), b21 = __ldg(b2 + 1);

    U64* sw = sP + warp * 512;
    int gw = blockIdx.x * 8 + warp;
    int stride = gridDim.x * 8 * 8;

    for (int base = gw * 8; base < N; base += stride) {
        __syncwarp();
        #pragma unroll
        for (int p = 0; p < 4; p++) {
            int r0 = base + 2 * p, r1 = r0 + 1;
            float4 x0 = {0,0,0,0}, x1 = {0,0,0,0};
            if (r0 < N) x0 = *reinterpret_cast<const float4*>(hin + (size_t)r0 * DD + lane * 4);
            if (r1 < N) x1 = *reinterpret_cast<const float4*>(hin + (size_t)r1 * DD + lane * 4);
            float2* dx = reinterpret_cast<float2*>(sw + p * 128);
            dx[lane * 4 + 0] = make_float2(x0.x, x1.x);
            dx[lane * 4 + 1] = make_float2(x0.y, x1.y);
            dx[lane * 4 + 2] = make_float2(x0.z, x1.z);
            dx[lane * 4 + 3] = make_float2(x0.w, x1.w);
        }
        __syncwarp();

        U64 acc[4][4];
        #pragma unroll
        for (int p = 0; p < 4; p++)
            #pragma unroll
            for (int c = 0; c < 4; c++) acc[p][c] = bp[c];

        #pragma unroll 4
        for (int k = 0; k < 128; k += 2) {
            float4 w0 = sW4[k * 32 + lane], w1 = sW4[k * 32 + 32 + lane];
            U64 w0p[4] = {pk2(w0.x,w0.x), pk2(w0.y,w0.y), pk2(w0.z,w0.z), pk2(w0.w,w0.w)};
            U64 w1p[4] = {pk2(w1.x,w1.x), pk2(w1.y,w1.y), pk2(w1.z,w1.z), pk2(w1.w,w1.w)};
            #pragma unroll
            for (int p = 0; p < 4; p++) {
                ulonglong2 xp = *reinterpret_cast<const ulonglong2*>(sw + p * 128 + k);
                #pragma unroll
                for (int c = 0; c < 4; c++) {
                    acc[p][c] = f2(xp.x, w0p[c], acc[p][c]);
                    acc[p][c] = f2(xp.y, w1p[c], acc[p][c]);
                }
            }
        }

        #pragma unroll
        for (int p = 0; p < 4; p++) {
            #pragma unroll
            for (int c = 0; c < 4; c++) {
                float lo, hi; upk2(acc[p][c], lo, hi);
                acc[p][c] = pk2(fmaxf(lo, 0.f), fmaxf(hi, 0.f));
            }
            U64 s = add2(add2(acc[p][0], acc[p][1]), add2(acc[p][2], acc[p][3]));
            #pragma unroll
            for (int o = 16; o; o >>= 1) s = add2(s, shfl64(s, o));
            U64 mu = mul2(s, INV128);
            U64 d[4];
            #pragma unroll
            for (int c = 0; c < 4; c++) d[c] = f2(mu, NEG1, acc[p][c]);
            U64 q = add2(add2(mul2(d[0], d[0]), mul2(d[1], d[1])),
                         add2(mul2(d[2], d[2]), mul2(d[3], d[3])));
            #pragma unroll
            for (int o = 16; o; o >>= 1) q = add2(q, shfl64(q, o));
            float ql, qh; upk2(q, ql, qh);
            float rl = rsqrtf(ql * 0.0078125f + 1e-5f);
            float rh = rsqrtf(qh * 0.0078125f + 1e-5f);

            float p0lo = 0.f, p1lo = 0.f, p0hi = 0.f, p1hi = 0.f;
            #pragma unroll
            for (int c = 0; c < 4; c++) {
                float dl, dh2; upk2(d[c], dl, dh2);
                float zl = dl * rl * gA[c] + bA[c];
                float zh = dh2 * rh * gA[c] + bA[c];
                p0lo += zl * w2c0[c]; p1lo += zl * w2c1[c];
                p0hi += zh * w2c0[c]; p1hi += zh * w2c1[c];
            }
            U64 P0 = pk2(p0lo, p0hi), P1 = pk2(p1lo, p1hi);
            #pragma unroll
            for (int o = 16; o; o >>= 1) {
                P0 = add2(P0, shfl64(P0, o));
                P1 = add2(P1, shfl64(P1, o));
            }
            if (lane == 0) {
                float a0, a1, c0, c1;
                upk2(P0, a0, a1); upk2(P1, c0, c1);
                int r0 = base + 2 * p, r1 = r0 + 1;
                if (r0 < N) { out[(size_t)r0 * 2 + 0] = a0 + b20; out[(size_t)r0 * 2 + 1] = c0 + b21; }
                if (r1 < N) { out[(size_t)r1 * 2 + 0] = a1 + b20; out[(size_t)r1 * 2 + 1] = c1 + b21; }
            }
        }
    }
}

// ---------------------------------------------------------------------------
extern "C" void kernel_launch(void* const* d_in, const int* in_sizes, int n_in,
                              void* d_out, int out_size) {
    const float* features = (const float*)d_in[0];
    const int*   ei       = (const int*)  d_in[1];
    const float* ew       = (const float*)d_in[2];
    const float* Wrel     = (const float*)d_in[3];
    const float* Wroot    = (const float*)d_in[4];
    const float* bias     = (const float*)d_in[5];
    const float* lng      = (const float*)d_in[6];
    const float* lnb      = (const float*)d_in[7];
    const float* alpha    = (const float*)d_in[8];
    const float* W1       = (const float*)d_in[9];
    const float* b1       = (const float*)d_in[10];
    const float* cg       = (const float*)d_in[11];
    const float* cb       = (const float*)d_in[12];
    const float* W2       = (const float*)d_in[13];
    const float* b2       = (const float*)d_in[14];

    int N = in_sizes[0] / DD;
    int E = in_sizes[1] / 2;
    int L = in_sizes[8];

    float *buf0, *buf1, *ewt;
    int *cnt, *off, *bsum, *esrc;
    cudaGetSymbolAddress((void**)&buf0, g_buf0);
    cudaGetSymbolAddress((void**)&buf1, g_buf1);
    cudaGetSymbolAddress((void**)&cnt,  g_cnt);
    cudaGetSymbolAddress((void**)&off,  g_off);
    cudaGetSymbolAddress((void**)&bsum, g_bsum);
    cudaGetSymbolAddress((void**)&esrc, g_esrc);
    cudaGetSymbolAddress((void**)&ewt,  g_ewt);

    int sm = 148;
    cudaDeviceGetAttribute(&sm, cudaDevAttrMultiProcessorCount, 0);

    size_t smemG = 229376;  // 128 KB weights + 96 KB staging
    size_t smemC = 98304;   // 64 KB + 32 KB
    cudaFuncSetAttribute(layer_kernel,      cudaFuncAttributeMaxDynamicSharedMemorySize, (int)smemG);
    cudaFuncSetAttribute(classifier_kernel, cudaFuncAttributeMaxDynamicSharedMemorySize, (int)smemC);

    // ---- CSR build (reused across all layers) ----
    int NB = (N + 1023) / 1024;
    cudaMemsetAsync(cnt, 0, (size_t)N * sizeof(int));
    hist_kernel <<<(E + 255) / 256, 256>>>(ei, cnt, E);
    scan1_kernel<<<NB, 1024>>>(cnt, off, bsum, N);
    scan2_kernel<<<1, 128>>>(bsum, off, NB, N);
    scan3_kernel<<<(N + 255) / 256, 256>>>(off, bsum, N);
    cudaMemsetAsync(cnt, 0, (size_t)N * sizeof(int));   // cursor
    place_kernel<<<(E + 255) / 256, 256>>>(ei, ew, off, cnt, esrc, ewt, E);

    const float* hin = features;
    float* pong[2] = { buf0, buf1 };
    for (int i = 0; i < L; i++) {
        float* hout = pong[i & 1];
        layer_kernel<<<sm, 384, smemG>>>(hin, off, esrc, ewt,
                                         Wrel  + (size_t)i * DD * DD,
                                         Wroot + (size_t)i * DD * DD,
                                         bias + i * DD, lng + i * DD, lnb + i * DD,
                                         alpha + i, hout, N);
        hin = hout;
    }
    classifier_kernel<<<2 * sm, 256, smemC>>>(hin, W1, b1, cg, cb, W2, b2,
                                              (float*)d_out, N);
}

// round 6
// speedup vs baseline: 1.4687x; 1.4687x over previous
#include <cuda_runtime.h>
#include <cstdint>

// ---------------------------------------------------------------------------
// GNN: L x { agg = scatter_add(h[src]*ew, dst); h = PReLU(LN(agg@Wrel + h@Wroot + b)) }
// then logits = LN(relu(h@W1+b1)) @ W2 + b2
// R6: layer GEMMs on tensor cores via mma.sync tf32 (arch-generic, sm_80+).
// ---------------------------------------------------------------------------

#define MAXN 100000
#define MAXE 1600000
#define DD   128
typedef unsigned long long U64;

__device__ float g_buf0[MAXN * DD];
__device__ float g_buf1[MAXN * DD];
__device__ float g_agg [MAXN * DD];
__device__ int   g_cnt [MAXN];
__device__ int   g_off [MAXN + 1];
__device__ int   g_bsum[128];
__device__ int   g_esrc[MAXE];
__device__ float g_ewt [MAXE];

// ---- packed f32x2 helpers (classifier) ----
__device__ __forceinline__ U64 pk2(float lo, float hi) {
    U64 r; asm("mov.b64 %0,{%1,%2};" : "=l"(r) : "f"(lo), "f"(hi)); return r;
}
__device__ __forceinline__ void upk2(U64 v, float& lo, float& hi) {
    asm("mov.b64 {%0,%1},%2;" : "=f"(lo), "=f"(hi) : "l"(v));
}
__device__ __forceinline__ U64 f2(U64 a, U64 b, U64 c) {
    asm("fma.rn.f32x2 %0,%1,%2,%0;" : "+l"(c) : "l"(a), "l"(b)); return c;
}
__device__ __forceinline__ U64 add2(U64 a, U64 b) {
    U64 r; asm("add.rn.f32x2 %0,%1,%2;" : "=l"(r) : "l"(a), "l"(b)); return r;
}
__device__ __forceinline__ U64 mul2(U64 a, U64 b) {
    U64 r; asm("mul.rn.f32x2 %0,%1,%2;" : "=l"(r) : "l"(a), "l"(b)); return r;
}
__device__ __forceinline__ U64 shfl64(U64 v, int o) {
    return (U64)__shfl_xor_sync(0xffffffffu, (long long)v, o);
}

__device__ __forceinline__ uint32_t tf32c(float f) {
    uint32_t r; asm("cvt.rna.tf32.f32 %0, %1;" : "=r"(r) : "f"(f)); return r;
}
__device__ __forceinline__ void mma8(float c[4], uint32_t a0, uint32_t a1,
                                     uint32_t a2, uint32_t a3,
                                     uint32_t b0, uint32_t b1) {
    asm volatile(
        "mma.sync.aligned.m16n8k8.row.col.f32.tf32.tf32.f32 "
        "{%0,%1,%2,%3},{%4,%5,%6,%7},{%8,%9},{%0,%1,%2,%3};"
        : "+f"(c[0]), "+f"(c[1]), "+f"(c[2]), "+f"(c[3])
        : "r"(a0), "r"(a1), "r"(a2), "r"(a3), "r"(b0), "r"(b1));
}

// ======================= CSR build (once per call) =========================
__global__ void hist_kernel(const int* __restrict__ ei, int* __restrict__ cnt, int E) {
    int e = blockIdx.x * blockDim.x + threadIdx.x;
    if (e < E) atomicAdd(cnt + __ldg(ei + E + e), 1);
}
__global__ void scan1_kernel(const int* __restrict__ cnt, int* __restrict__ off,
                             int* __restrict__ bsum, int N) {
    __shared__ int s[1024];
    int tid = threadIdx.x;
    int i = blockIdx.x * 1024 + tid;
    int v = (i < N) ? cnt[i] : 0;
    s[tid] = v; __syncthreads();
    #pragma unroll
    for (int d = 1; d < 1024; d <<= 1) {
        int t = (tid >= d) ? s[tid - d] : 0;
        __syncthreads();
        s[tid] += t;
        __syncthreads();
    }
    if (i < N) off[i] = s[tid] - v;
    if (tid == 1023) bsum[blockIdx.x] = s[1023];
}
__global__ void scan2_kernel(int* __restrict__ bsum, int* __restrict__ off,
                             int NB, int N) {
    __shared__ int s[128];
    int tid = threadIdx.x;
    int v = (tid < NB) ? bsum[tid] : 0;
    s[tid] = v; __syncthreads();
    #pragma unroll
    for (int d = 1; d < 128; d <<= 1) {
        int t = (tid >= d) ? s[tid - d] : 0;
        __syncthreads();
        s[tid] += t;
        __syncthreads();
    }
    if (tid < NB) bsum[tid] = s[tid] - v;
    if (tid == 127) off[N] = s[127];
}
__global__ void scan3_kernel(int* __restrict__ off, const int* __restrict__ bsum, int N) {
    int i = blockIdx.x * blockDim.x + threadIdx.x;
    if (i < N) off[i] += bsum[i >> 10];
}
__global__ void place_kernel(const int* __restrict__ ei, const float* __restrict__ ew,
                             const int* __restrict__ off, int* __restrict__ cursor,
                             int* __restrict__ esrc, float* __restrict__ ewt, int E) {
    int e = blockIdx.x * blockDim.x + threadIdx.x;
    if (e >= E) return;
    int src = __ldg(ei + e);
    int dst = __ldg(ei + E + e);
    int pos = off[dst] + atomicAdd(cursor + dst, 1);
    esrc[pos] = src;
    ewt[pos]  = __ldg(ew + e);
}

// ======================= Aggregation: warp per node ========================
__global__ __launch_bounds__(256)
void gather_kernel(const float* __restrict__ h,
                   const int*   __restrict__ off,
                   const int*   __restrict__ esrc,
                   const float* __restrict__ ewt,
                   float*       __restrict__ agg, int N) {
    int warp = threadIdx.x >> 5, lane = threadIdx.x & 31;
    int node = blockIdx.x * 8 + warp;
    if (node >= N) return;
    int beg = __ldg(off + node), end = __ldg(off + node + 1);
    float4 acc = {0.f, 0.f, 0.f, 0.f};
    int e = beg;
    for (; e + 1 < end; e += 2) {
        int   s0 = __ldg(esrc + e),  s1 = __ldg(esrc + e + 1);
        float w0 = __ldg(ewt + e),   w1 = __ldg(ewt + e + 1);
        float4 v0 = *reinterpret_cast<const float4*>(h + (size_t)s0 * DD + lane * 4);
        float4 v1 = *reinterpret_cast<const float4*>(h + (size_t)s1 * DD + lane * 4);
        acc.x = fmaf(w0, v0.x, fmaf(w1, v1.x, acc.x));
        acc.y = fmaf(w0, v0.y, fmaf(w1, v1.y, acc.y));
        acc.z = fmaf(w0, v0.z, fmaf(w1, v1.z, acc.z));
        acc.w = fmaf(w0, v0.w, fmaf(w1, v1.w, acc.w));
    }
    if (e < end) {
        int   s0 = __ldg(esrc + e);
        float w0 = __ldg(ewt + e);
        float4 v0 = *reinterpret_cast<const float4*>(h + (size_t)s0 * DD + lane * 4);
        acc.x = fmaf(w0, v0.x, acc.x);
        acc.y = fmaf(w0, v0.y, acc.y);
        acc.z = fmaf(w0, v0.z, acc.z);
        acc.w = fmaf(w0, v0.w, acc.w);
    }
    *reinterpret_cast<float4*>(agg + (size_t)node * DD + lane * 4) = acc;
}

// ============== Layer GEMM via mma.sync tf32 ===============================
// Per block: 128-row tile; 8 warps, warp = one 16-row m-tile x 128 cols.
// SMEM holds A (64KB, fragment order) + Wrel^f + Wroot^f (64KB each, fragment
// order). Two accumulation halves: A=agg vs Wrel, then A=h vs Wroot.
// Epilogue: bias + LN (lane-quad reduction) + PReLU, direct STG.64.
__global__ __launch_bounds__(256, 1)
void layer_mma_kernel(const float* __restrict__ hin,
                      const float* __restrict__ agg,
                      const float* __restrict__ Wrel,
                      const float* __restrict__ Wroot,
                      const float* __restrict__ bias,
                      const float* __restrict__ lng,
                      const float* __restrict__ lnb,
                      const float* __restrict__ alpha,
                      float*       __restrict__ hout,
                      int N) {
    extern __shared__ uint32_t smemu[];
    uint32_t* sA  = smemu;            // 16384 u32 (64 KB)
    uint32_t* sBr = smemu + 16384;    // 64 KB
    uint32_t* sBo = smemu + 32768;    // 64 KB
    __shared__ float sBias[128], sG[128], sB[128];

    int tid = threadIdx.x, wid = tid >> 5, lane = tid & 31;
    int g = lane >> 2, t = lane & 3;

    // ---- stage weights in B-fragment order ----
    // B frag (col-major 8x8 per tile): b0=(k=kk*8+t, n=nt*8+g), b1=(k+4).
    // sB[((nt*8+kkp)*32 + g*4 + t)*4 + j], j = (kk&1)*2 + breg.
    for (int idx = tid; idx < 4096; idx += 256) {
        int k = idx >> 5, n4 = (idx & 31) * 4;
        float4 vr = *reinterpret_cast<const float4*>(Wrel  + (size_t)k * 128 + n4);
        float4 vo = *reinterpret_cast<const float4*>(Wroot + (size_t)k * 128 + n4);
        int kk = k >> 3, t8 = k & 7, breg = t8 >> 2, tt = t8 & 3;
        int j = ((kk & 1) << 1) + breg, kkp = kk >> 1;
        float vrA[4] = {vr.x, vr.y, vr.z, vr.w};
        float voA[4] = {vo.x, vo.y, vo.z, vo.w};
        #pragma unroll
        for (int m = 0; m < 4; m++) {
            int n = n4 + m, nt = n >> 3, gg = n & 7;
            int base = ((nt * 8 + kkp) * 32 + gg * 4 + tt) * 4 + j;
            sBr[base] = tf32c(vrA[m]);
            sBo[base] = tf32c(voA[m]);
        }
    }
    if (tid < 128) {
        sBias[tid] = __ldg(bias + tid);
        sG[tid]    = __ldg(lng + tid);
        sB[tid]    = __ldg(lnb + tid);
    }
    __syncthreads();

    float al = __ldg(alpha);

    for (int tile = blockIdx.x; tile * 128 < N; tile += gridDim.x) {
        int rbase = tile * 128;
        float c[16][4];
        #pragma unroll
        for (int nt = 0; nt < 16; nt++)
            #pragma unroll
            for (int j = 0; j < 4; j++) c[nt][j] = 0.f;

        #pragma unroll
        for (int half = 0; half < 2; half++) {
            const float*    src = half ? hin : agg;
            const uint32_t* sBf = half ? sBo : sBr;
            // ---- stage A in fragment order ----
            // A frag: a0=(row=mt*16+g, k=kk*8+t) a1=(row+8) a2=(k+4) a3=(row+8,k+4)
            // sA[((mt*16+kk)*32 + g*4 + t)*4 + j], j = khi*2 + rowhi.
            for (int idx = tid; idx < 4096; idx += 256) {
                int rl = idx >> 5, k4 = (idx & 31) * 4;
                int r = rbase + rl;
                float4 v = (r < N)
                    ? *reinterpret_cast<const float4*>(src + (size_t)r * 128 + k4)
                    : make_float4(0.f, 0.f, 0.f, 0.f);
                int mt = rl >> 4, r16 = rl & 15, g8 = r16 & 7, rowhi = r16 >> 3;
                int kk = k4 >> 3, khi = (k4 & 7) >> 2;
                int j = khi * 2 + rowhi;
                int bidx = ((mt * 16 + kk) * 32 + g8 * 4) * 4 + j;
                sA[bidx +  0] = tf32c(v.x);   // t=0
                sA[bidx +  4] = tf32c(v.y);   // t=1
                sA[bidx +  8] = tf32c(v.z);
                sA[bidx + 12] = tf32c(v.w);
            }
            __syncthreads();
            // ---- MMA loop ----
            const uint32_t* aBase = sA + (wid * 16) * 32 * 4;
            #pragma unroll
            for (int kkp = 0; kkp < 8; kkp++) {
                uint4 aE = *reinterpret_cast<const uint4*>(aBase + ((2*kkp)   * 32 + lane) * 4);
                uint4 aO = *reinterpret_cast<const uint4*>(aBase + ((2*kkp+1) * 32 + lane) * 4);
                #pragma unroll
                for (int nt = 0; nt < 16; nt++) {
                    uint4 bv = *reinterpret_cast<const uint4*>(sBf + ((nt * 8 + kkp) * 32 + lane) * 4);
                    mma8(c[nt], aE.x, aE.y, aE.z, aE.w, bv.x, bv.y);
                    mma8(c[nt], aO.x, aO.y, aO.z, aO.w, bv.z, bv.w);
                }
            }
            __syncthreads();   // all warps done reading sA before restage
        }

        // ---- epilogue: bias + LN + PReLU ----
        // lane holds rows {r0=rbase+wid*16+g, r1=r0+8}, cols nt*8+2t(+1).
        #pragma unroll
        for (int nt = 0; nt < 16; nt++) {
            int col = nt * 8 + 2 * t;
            float b0 = sBias[col], b1 = sBias[col + 1];
            c[nt][0] += b0; c[nt][1] += b1;
            c[nt][2] += b0; c[nt][3] += b1;
        }
        float s0 = 0.f, s1 = 0.f;
        #pragma unroll
        for (int nt = 0; nt < 16; nt++) {
            s0 += c[nt][0] + c[nt][1];
            s1 += c[nt][2] + c[nt][3];
        }
        s0 += __shfl_xor_sync(0xffffffffu, s0, 1);
        s0 += __shfl_xor_sync(0xffffffffu, s0, 2);
        s1 += __shfl_xor_sync(0xffffffffu, s1, 1);
        s1 += __shfl_xor_sync(0xffffffffu, s1, 2);
        float mu0 = s0 * 0.0078125f, mu1 = s1 * 0.0078125f;
        float q0 = 0.f, q1 = 0.f;
        #pragma unroll
        for (int nt = 0; nt < 16; nt++) {
            c[nt][0] -= mu0; c[nt][1] -= mu0;
            c[nt][2] -= mu1; c[nt][3] -= mu1;
            q0 = fmaf(c[nt][0], c[nt][0], fmaf(c[nt][1], c[nt][1], q0));
            q1 = fmaf(c[nt][2], c[nt][2], fmaf(c[nt][3], c[nt][3], q1));
        }
        q0 += __shfl_xor_sync(0xffffffffu, q0, 1);
        q0 += __shfl_xor_sync(0xffffffffu, q0, 2);
        q1 += __shfl_xor_sync(0xffffffffu, q1, 1);
        q1 += __shfl_xor_sync(0xffffffffu, q1, 2);
        float rstd0 = rsqrtf(q0 * 0.0078125f + 1e-5f);
        float rstd1 = rsqrtf(q1 * 0.0078125f + 1e-5f);

        int r0 = rbase + wid * 16 + g, r1 = r0 + 8;
        bool w0ok = r0 < N, w1ok = r1 < N;
        #pragma unroll
        for (int nt = 0; nt < 16; nt++) {
            int col = nt * 8 + 2 * t;
            float g0 = sG[col], g1 = sG[col + 1];
            float e0 = sB[col], e1 = sB[col + 1];
            float y00 = c[nt][0] * rstd0 * g0 + e0;
            float y01 = c[nt][1] * rstd0 * g1 + e1;
            float y10 = c[nt][2] * rstd1 * g0 + e0;
            float y11 = c[nt][3] * rstd1 * g1 + e1;
            y00 = y00 >= 0.f ? y00 : al * y00;
            y01 = y01 >= 0.f ? y01 : al * y01;
            y10 = y10 >= 0.f ? y10 : al * y10;
            y11 = y11 >= 0.f ? y11 : al * y11;
            if (w0ok) *reinterpret_cast<float2*>(hout + (size_t)r0 * 128 + col) = make_float2(y00, y01);
            if (w1ok) *reinterpret_cast<float2*>(hout + (size_t)r1 * 128 + col) = make_float2(y10, y11);
        }
        __syncthreads();   // before next tile overwrites sA
    }
}

// ======================= Classifier (FFMA2) ================================
__global__ __launch_bounds__(256, 2)
void classifier_kernel(const float* __restrict__ hin,
                       const float* __restrict__ W1,
                       const float* __restrict__ b1,
                       const float* __restrict__ lng,
                       const float* __restrict__ lnb,
                       const float* __restrict__ W2,
                       const float* __restrict__ b2,
                       float*       __restrict__ out,
                       int N) {
    extern __shared__ float smemf[];
    float4* sW4 = reinterpret_cast<float4*>(smemf);
    U64*    sP  = reinterpret_cast<U64*>(smemf + 16384);

    int tid = threadIdx.x, lane = tid & 31, warp = tid >> 5;

    const float4* W14 = reinterpret_cast<const float4*>(W1);
    #pragma unroll
    for (int i = tid; i < 4096; i += 256) sW4[i] = W14[i];
    __syncthreads();

    float4 b1v = *reinterpret_cast<const float4*>(b1  + lane * 4);
    float4 gg  = *reinterpret_cast<const float4*>(lng + lane * 4);
    float4 bb  = *reinterpret_cast<const float4*>(lnb + lane * 4);
    float gA[4] = {gg.x, gg.y, gg.z, gg.w};
    float bA[4] = {bb.x, bb.y, bb.z, bb.w};
    U64 bp[4] = {pk2(b1v.x, b1v.x), pk2(b1v.y, b1v.y),
                 pk2(b1v.z, b1v.z), pk2(b1v.w, b1v.w)};
    const U64 NEG1   = pk2(-1.f, -1.f);
    const U64 INV128 = pk2(0.0078125f, 0.0078125f);

    float w2c0[4], w2c1[4];
    #pragma unroll
    for (int c = 0; c < 4; c++) {
        w2c0[c] = __ldg(W2 + (lane * 4 + c) * 2 + 0);
        w2c1[c] = __ldg(W2 + (lane * 4 + c) * 2 + 1);
    }
    float b20 = __ldg(b2 + 0), b21 = __ldg(b2 + 1);

    U64* sw = sP + warp * 512;
    int gw = blockIdx.x * 8 + warp;
    int stride = gridDim.x * 8 * 8;

    for (int base = gw * 8; base < N; base += stride) {
        __syncwarp();
        #pragma unroll
        for (int p = 0; p < 4; p++) {
            int r0 = base + 2 * p, r1 = r0 + 1;
            float4 x0 = {0,0,0,0}, x1 = {0,0,0,0};
            if (r0 < N) x0 = *reinterpret_cast<const float4*>(hin + (size_t)r0 * DD + lane * 4);
            if (r1 < N) x1 = *reinterpret_cast<const float4*>(hin + (size_t)r1 * DD + lane * 4);
            float2* dx = reinterpret_cast<float2*>(sw + p * 128);
            dx[lane * 4 + 0] = make_float2(x0.x, x1.x);
            dx[lane * 4 + 1] = make_float2(x0.y, x1.y);
            dx[lane * 4 + 2] = make_float2(x0.z, x1.z);
            dx[lane * 4 + 3] = make_float2(x0.w, x1.w);
        }
        __syncwarp();

        U64 acc[4][4];
        #pragma unroll
        for (int p = 0; p < 4; p++)
            #pragma unroll
            for (int c = 0; c < 4; c++) acc[p][c] = bp[c];

        #pragma unroll 4
        for (int k = 0; k < 128; k += 2) {
            float4 w0 = sW4[k * 32 + lane], w1 = sW4[k * 32 + 32 + lane];
            U64 w0p[4] = {pk2(w0.x,w0.x), pk2(w0.y,w0.y), pk2(w0.z,w0.z), pk2(w0.w,w0.w)};
            U64 w1p[4] = {pk2(w1.x,w1.x), pk2(w1.y,w1.y), pk2(w1.z,w1.z), pk2(w1.w,w1.w)};
            #pragma unroll
            for (int p = 0; p < 4; p++) {
                ulonglong2 xp = *reinterpret_cast<const ulonglong2*>(sw + p * 128 + k);
                #pragma unroll
                for (int c = 0; c < 4; c++) {
                    acc[p][c] = f2(xp.x, w0p[c], acc[p][c]);
                    acc[p][c] = f2(xp.y, w1p[c], acc[p][c]);
                }
            }
        }

        #pragma unroll
        for (int p = 0; p < 4; p++) {
            #pragma unroll
            for (int c = 0; c < 4; c++) {
                float lo, hi; upk2(acc[p][c], lo, hi);
                acc[p][c] = pk2(fmaxf(lo, 0.f), fmaxf(hi, 0.f));
            }
            U64 s = add2(add2(acc[p][0], acc[p][1]), add2(acc[p][2], acc[p][3]));
            #pragma unroll
            for (int o = 16; o; o >>= 1) s = add2(s, shfl64(s, o));
            U64 mu = mul2(s, INV128);
            U64 d[4];
            #pragma unroll
            for (int c = 0; c < 4; c++) d[c] = f2(mu, NEG1, acc[p][c]);
            U64 q = add2(add2(mul2(d[0], d[0]), mul2(d[1], d[1])),
                         add2(mul2(d[2], d[2]), mul2(d[3], d[3])));
            #pragma unroll
            for (int o = 16; o; o >>= 1) q = add2(q, shfl64(q, o));
            float ql, qh; upk2(q, ql, qh);
            float rl = rsqrtf(ql * 0.0078125f + 1e-5f);
            float rh = rsqrtf(qh * 0.0078125f + 1e-5f);

            float p0lo = 0.f, p1lo = 0.f, p0hi = 0.f, p1hi = 0.f;
            #pragma unroll
            for (int c = 0; c < 4; c++) {
                float dl, dh2; upk2(d[c], dl, dh2);
                float zl = dl * rl * gA[c] + bA[c];
                float zh = dh2 * rh * gA[c] + bA[c];
                p0lo += zl * w2c0[c]; p1lo += zl * w2c1[c];
                p0hi += zh * w2c0[c]; p1hi += zh * w2c1[c];
            }
            U64 P0 = pk2(p0lo, p0hi), P1 = pk2(p1lo, p1hi);
            #pragma unroll
            for (int o = 16; o; o >>= 1) {
                P0 = add2(P0, shfl64(P0, o));
                P1 = add2(P1, shfl64(P1, o));
            }
            if (lane == 0) {
                float a0, a1, c0, c1;
                upk2(P0, a0, a1); upk2(P1, c0, c1);
                int r0 = base + 2 * p, r1 = r0 + 1;
                if (r0 < N) { out[(size_t)r0 * 2 + 0] = a0 + b20; out[(size_t)r0 * 2 + 1] = c0 + b21; }
                if (r1 < N) { out[(size_t)r1 * 2 + 0] = a1 + b20; out[(size_t)r1 * 2 + 1] = c1 + b21; }
            }
        }
    }
}

// ---------------------------------------------------------------------------
extern "C" void kernel_launch(void* const* d_in, const int* in_sizes, int n_in,
                              void* d_out, int out_size) {
    const float* features = (const float*)d_in[0];
    const int*   ei       = (const int*)  d_in[1];
    const float* ew       = (const float*)d_in[2];
    const float* Wrel     = (const float*)d_in[3];
    const float* Wroot    = (const float*)d_in[4];
    const float* bias     = (const float*)d_in[5];
    const float* lng      = (const float*)d_in[6];
    const float* lnb      = (const float*)d_in[7];
    const float* alpha    = (const float*)d_in[8];
    const float* W1       = (const float*)d_in[9];
    const float* b1       = (const float*)d_in[10];
    const float* cg       = (const float*)d_in[11];
    const float* cb       = (const float*)d_in[12];
    const float* W2       = (const float*)d_in[13];
    const float* b2       = (const float*)d_in[14];

    int N = in_sizes[0] / DD;
    int E = in_sizes[1] / 2;
    int L = in_sizes[8];

    float *buf0, *buf1, *agg, *ewt;
    int *cnt, *off, *bsum, *esrc;
    cudaGetSymbolAddress((void**)&buf0, g_buf0);
    cudaGetSymbolAddress((void**)&buf1, g_buf1);
    cudaGetSymbolAddress((void**)&agg,  g_agg);
    cudaGetSymbolAddress((void**)&cnt,  g_cnt);
    cudaGetSymbolAddress((void**)&off,  g_off);
    cudaGetSymbolAddress((void**)&bsum, g_bsum);
    cudaGetSymbolAddress((void**)&esrc, g_esrc);
    cudaGetSymbolAddress((void**)&ewt,  g_ewt);

    int sm = 148;
    cudaDeviceGetAttribute(&sm, cudaDevAttrMultiProcessorCount, 0);

    size_t smemL = 196608;  // 3 x 64 KB
    size_t smemC = 98304;
    cudaFuncSetAttribute(layer_mma_kernel,  cudaFuncAttributeMaxDynamicSharedMemorySize, (int)smemL);
    cudaFuncSetAttribute(classifier_kernel, cudaFuncAttributeMaxDynamicSharedMemorySize, (int)smemC);

    // ---- CSR build ----
    int NB = (N + 1023) / 1024;
    cudaMemsetAsync(cnt, 0, (size_t)N * sizeof(int));
    hist_kernel <<<(E + 255) / 256, 256>>>(ei, cnt, E);
    scan1_kernel<<<NB, 1024>>>(cnt, off, bsum, N);
    scan2_kernel<<<1, 128>>>(bsum, off, NB, N);
    scan3_kernel<<<(N + 255) / 256, 256>>>(off, bsum, N);
    cudaMemsetAsync(cnt, 0, (size_t)N * sizeof(int));
    place_kernel<<<(E + 255) / 256, 256>>>(ei, ew, off, cnt, esrc, ewt, E);

    int gatherBlocks = (N + 7) / 8;

    const float* hin = features;
    float* pong[2] = { buf0, buf1 };
    for (int i = 0; i < L; i++) {
        float* hout = pong[i & 1];
        gather_kernel<<<gatherBlocks, 256>>>(hin, off, esrc, ewt, agg, N);
        layer_mma_kernel<<<sm, 256, smemL>>>(hin, agg,
                                             Wrel  + (size_t)i * DD * DD,
                                             Wroot + (size_t)i * DD * DD,
                                             bias + i * DD, lng + i * DD, lnb + i * DD,
                                             alpha + i, hout, N);
        hin = hout;
    }
    classifier_kernel<<<2 * sm, 256, smemC>>>(hin, W1, b1, cg, cb, W2, b2,
                                              (float*)d_out, N);
}

// round 7
// speedup vs baseline: 1.9883x; 1.3538x over previous
#include <cuda_runtime.h>
#include <cstdint>

// ---------------------------------------------------------------------------
// GNN: L x { agg = scatter_add(h[src]*ew, dst); h = PReLU(LN(agg@Wrel + h@Wroot + b)) }
// then logits = LN(relu(h@W1+b1)) @ W2 + b2
// R7: warp-level tf32 mma with A direct-from-global (no A smem, no staging
//     conflicts, full B reuse: warp tile = 32 rows x 128 cols). CSR build
//     trimmed to 5 launches (no memsets, scan3 folded into place/gather).
// ---------------------------------------------------------------------------

#define MAXN 100000
#define MAXE 1600000
#define DD   128
typedef unsigned long long U64;

__device__ float g_buf0[MAXN * DD];
__device__ float g_buf1[MAXN * DD];
__device__ float g_agg [MAXN * DD];
__device__ int   g_cnt [MAXN];        // zero at entry of every call (see place)
__device__ int   g_off [MAXN + 1];
__device__ int   g_bsum[128];
__device__ int   g_esrc[MAXE];
__device__ float g_ewt [MAXE];

// ---- packed f32x2 helpers (classifier) ----
__device__ __forceinline__ U64 pk2(float lo, float hi) {
    U64 r; asm("mov.b64 %0,{%1,%2};" : "=l"(r) : "f"(lo), "f"(hi)); return r;
}
__device__ __forceinline__ void upk2(U64 v, float& lo, float& hi) {
    asm("mov.b64 {%0,%1},%2;" : "=f"(lo), "=f"(hi) : "l"(v));
}
__device__ __forceinline__ U64 f2(U64 a, U64 b, U64 c) {
    asm("fma.rn.f32x2 %0,%1,%2,%0;" : "+l"(c) : "l"(a), "l"(b)); return c;
}
__device__ __forceinline__ U64 add2(U64 a, U64 b) {
    U64 r; asm("add.rn.f32x2 %0,%1,%2;" : "=l"(r) : "l"(a), "l"(b)); return r;
}
__device__ __forceinline__ U64 mul2(U64 a, U64 b) {
    U64 r; asm("mul.rn.f32x2 %0,%1,%2;" : "=l"(r) : "l"(a), "l"(b)); return r;
}
__device__ __forceinline__ U64 shfl64(U64 v, int o) {
    return (U64)__shfl_xor_sync(0xffffffffu, (long long)v, o);
}

__device__ __forceinline__ uint32_t tf32c(float f) {
    uint32_t r; asm("cvt.rna.tf32.f32 %0, %1;" : "=r"(r) : "f"(f)); return r;
}
__device__ __forceinline__ void mma8(float c[4], uint32_t a0, uint32_t a1,
                                     uint32_t a2, uint32_t a3,
                                     uint32_t b0, uint32_t b1) {
    asm volatile(
        "mma.sync.aligned.m16n8k8.row.col.f32.tf32.tf32.f32 "
        "{%0,%1,%2,%3},{%4,%5,%6,%7},{%8,%9},{%0,%1,%2,%3};"
        : "+f"(c[0]), "+f"(c[1]), "+f"(c[2]), "+f"(c[3])
        : "r"(a0), "r"(a1), "r"(a2), "r"(a3), "r"(b0), "r"(b1));
}

// ======================= CSR build (5 launches, no memsets) ================
__global__ void hist_kernel(const int* __restrict__ ei, int* __restrict__ cnt, int E) {
    int e = blockIdx.x * blockDim.x + threadIdx.x;
    if (e < E) atomicAdd(cnt + __ldg(ei + E + e), 1);
}
__global__ void scan1_kernel(const int* __restrict__ cnt, int* __restrict__ off,
                             int* __restrict__ bsum, int N) {
    __shared__ int s[1024];
    int tid = threadIdx.x;
    int i = blockIdx.x * 1024 + tid;
    int v = (i < N) ? cnt[i] : 0;
    s[tid] = v; __syncthreads();
    #pragma unroll
    for (int d = 1; d < 1024; d <<= 1) {
        int t = (tid >= d) ? s[tid - d] : 0;
        __syncthreads();
        s[tid] += t;
        __syncthreads();
    }
    if (i < N) off[i] = s[tid] - v;          // block-local exclusive
    if (tid == 1023) bsum[blockIdx.x] = s[1023];
}
__global__ void scan2_kernel(int* __restrict__ bsum, int* __restrict__ off,
                             int NB, int N) {
    __shared__ int s[128];
    int tid = threadIdx.x;
    int v = (tid < NB) ? bsum[tid] : 0;
    s[tid] = v; __syncthreads();
    #pragma unroll
    for (int d = 1; d < 128; d <<= 1) {
        int t = (tid >= d) ? s[tid - d] : 0;
        __syncthreads();
        s[tid] += t;
        __syncthreads();
    }
    if (tid < NB) bsum[tid] = s[tid] - v;    // exclusive block sums
    if (tid == 127) off[N] = s[127];         // grand total (final value)
}
// place: cursor counts down from hist counts back to zero -> cnt is all-zero
// at the end of every call (and at module load), so no memset is needed.
__global__ void place_kernel(const int* __restrict__ ei, const float* __restrict__ ew,
                             const int* __restrict__ off, const int* __restrict__ bsum,
                             int* __restrict__ cursor,
                             int* __restrict__ esrc, float* __restrict__ ewt, int E) {
    int e = blockIdx.x * blockDim.x + threadIdx.x;
    if (e >= E) return;
    int src = __ldg(ei + e);
    int dst = __ldg(ei + E + e);
    int pos = off[dst] + bsum[dst >> 10] + (atomicSub(cursor + dst, 1) - 1);
    esrc[pos] = src;
    ewt[pos]  = __ldg(ew + e);
}

// ======================= Aggregation: warp per node ========================
__global__ __launch_bounds__(256)
void gather_kernel(const float* __restrict__ h,
                   const int*   __restrict__ off,
                   const int*   __restrict__ bsum,
                   const int*   __restrict__ esrc,
                   const float* __restrict__ ewt,
                   float*       __restrict__ agg, int N) {
    int warp = threadIdx.x >> 5, lane = threadIdx.x & 31;
    int node = blockIdx.x * 8 + warp;
    if (node >= N) return;
    int beg = __ldg(off + node) + __ldg(bsum + (node >> 10));
    int end = (node + 1 == N) ? __ldg(off + N)
                              : __ldg(off + node + 1) + __ldg(bsum + ((node + 1) >> 10));
    float4 acc = {0.f, 0.f, 0.f, 0.f};
    int e = beg;
    for (; e + 1 < end; e += 2) {
        int   s0 = __ldg(esrc + e),  s1 = __ldg(esrc + e + 1);
        float w0 = __ldg(ewt + e),   w1 = __ldg(ewt + e + 1);
        float4 v0 = *reinterpret_cast<const float4*>(h + (size_t)s0 * DD + lane * 4);
        float4 v1 = *reinterpret_cast<const float4*>(h + (size_t)s1 * DD + lane * 4);
        acc.x = fmaf(w0, v0.x, fmaf(w1, v1.x, acc.x));
        acc.y = fmaf(w0, v0.y, fmaf(w1, v1.y, acc.y));
        acc.z = fmaf(w0, v0.z, fmaf(w1, v1.z, acc.z));
        acc.w = fmaf(w0, v0.w, fmaf(w1, v1.w, acc.w));
    }
    if (e < end) {
        int   s0 = __ldg(esrc + e);
        float w0 = __ldg(ewt + e);
        float4 v0 = *reinterpret_cast<const float4*>(h + (size_t)s0 * DD + lane * 4);
        acc.x = fmaf(w0, v0.x, acc.x);
        acc.y = fmaf(w0, v0.y, acc.y);
        acc.z = fmaf(w0, v0.z, acc.z);
        acc.w = fmaf(w0, v0.w, acc.w);
    }
    *reinterpret_cast<float4*>(agg + (size_t)node * DD + lane * 4) = acc;
}

// ============== Layer GEMM via warp-level mma.sync tf32 ====================
// Warp unit = 32 rows x 128 cols. A fragments loaded straight from global
// (each 32B sector fully used; no A smem). B = both weights in fragment-order
// SMEM (conflict-free uint4 LDS), staged once. No per-tile syncs.
__global__ __launch_bounds__(256, 1)
void layer_mma_kernel(const float* __restrict__ hin,
                      const float* __restrict__ agg,
                      const float* __restrict__ Wrel,
                      const float* __restrict__ Wroot,
                      const float* __restrict__ bias,
                      const float* __restrict__ lng,
                      const float* __restrict__ lnb,
                      const float* __restrict__ alpha,
                      float*       __restrict__ hout,
                      int N) {
    extern __shared__ uint32_t smemu[];
    uint32_t* sBr = smemu;            // 64 KB Wrel fragments
    uint32_t* sBo = smemu + 16384;    // 64 KB Wroot fragments
    __shared__ float sBias[128], sG[128], sB2[128];

    int tid = threadIdx.x, wid = tid >> 5, lane = tid & 31;
    int g = lane >> 2, t = lane & 3;

    // ---- stage weights in B-fragment order (verified layout from R6) ----
    for (int idx = tid; idx < 4096; idx += 256) {
        int k = idx >> 5, n4 = (idx & 31) * 4;
        float4 vr = *reinterpret_cast<const float4*>(Wrel  + (size_t)k * 128 + n4);
        float4 vo = *reinterpret_cast<const float4*>(Wroot + (size_t)k * 128 + n4);
        int kk = k >> 3, t8 = k & 7, breg = t8 >> 2, tt = t8 & 3;
        int j = ((kk & 1) << 1) + breg, kkp = kk >> 1;
        float vrA[4] = {vr.x, vr.y, vr.z, vr.w};
        float voA[4] = {vo.x, vo.y, vo.z, vo.w};
        #pragma unroll
        for (int m = 0; m < 4; m++) {
            int n = n4 + m, nt = n >> 3, gg = n & 7;
            int base = ((nt * 8 + kkp) * 32 + gg * 4 + tt) * 4 + j;
            sBr[base] = tf32c(vrA[m]);
            sBo[base] = tf32c(voA[m]);
        }
    }
    if (tid < 128) {
        sBias[tid] = __ldg(bias + tid);
        sG[tid]    = __ldg(lng + tid);
        sB2[tid]   = __ldg(lnb + tid);
    }
    __syncthreads();

    float al = __ldg(alpha);
    int numUnits = (N + 31) >> 5;
    int ustride  = gridDim.x * 8;

    for (int unit = blockIdx.x * 8 + wid; unit < numUnits; unit += ustride) {
        int R0 = unit * 32;
        float c[2][16][4];
        #pragma unroll
        for (int mt = 0; mt < 2; mt++)
            #pragma unroll
            for (int nt = 0; nt < 16; nt++)
                #pragma unroll
                for (int j = 0; j < 4; j++) c[mt][nt][j] = 0.f;

        #pragma unroll
        for (int half = 0; half < 2; half++) {
            const float*    src = half ? hin : agg;
            const uint32_t* sBf = half ? sBo : sBr;

            // per-lane row pointers (offset by t so k offsets are immediates)
            const float* rp[2][2];
            bool rv[2][2];
            #pragma unroll
            for (int mt = 0; mt < 2; mt++)
                #pragma unroll
                for (int rh = 0; rh < 2; rh++) {
                    int r = R0 + mt * 16 + g + 8 * rh;
                    rv[mt][rh] = r < N;
                    rp[mt][rh] = src + (size_t)r * 128 + t;
                }

            uint32_t a[2][2][8];   // [buf][mt][v]  v:0..3 kkE, 4..7 kkO
            #pragma unroll
            for (int mt = 0; mt < 2; mt++) {
                #pragma unroll
                for (int q = 0; q < 2; q++) {   // q=0: kkE (ofs 0), q=1: kkO (ofs 8)
                    int o = q * 8;
                    a[0][mt][q*4+0] = tf32c(rv[mt][0] ? rp[mt][0][o]     : 0.f);
                    a[0][mt][q*4+1] = tf32c(rv[mt][1] ? rp[mt][1][o]     : 0.f);
                    a[0][mt][q*4+2] = tf32c(rv[mt][0] ? rp[mt][0][o + 4] : 0.f);
                    a[0][mt][q*4+3] = tf32c(rv[mt][1] ? rp[mt][1][o + 4] : 0.f);
                }
            }

            #pragma unroll
            for (int kkp = 0; kkp < 8; kkp++) {
                int cur = kkp & 1;
                if (kkp < 7) {
                    int kb = (kkp + 1) * 16;
                    #pragma unroll
                    for (int mt = 0; mt < 2; mt++) {
                        #pragma unroll
                        for (int q = 0; q < 2; q++) {
                            int o = kb + q * 8;
                            a[cur^1][mt][q*4+0] = tf32c(rv[mt][0] ? rp[mt][0][o]     : 0.f);
                            a[cur^1][mt][q*4+1] = tf32c(rv[mt][1] ? rp[mt][1][o]     : 0.f);
                            a[cur^1][mt][q*4+2] = tf32c(rv[mt][0] ? rp[mt][0][o + 4] : 0.f);
                            a[cur^1][mt][q*4+3] = tf32c(rv[mt][1] ? rp[mt][1][o + 4] : 0.f);
                        }
                    }
                }
                #pragma unroll
                for (int nt = 0; nt < 16; nt++) {
                    uint4 bv = *reinterpret_cast<const uint4*>(
                        sBf + ((nt * 8 + kkp) * 32 + lane) * 4);
                    mma8(c[0][nt], a[cur][0][0], a[cur][0][1], a[cur][0][2], a[cur][0][3], bv.x, bv.y);
                    mma8(c[0][nt], a[cur][0][4], a[cur][0][5], a[cur][0][6], a[cur][0][7], bv.z, bv.w);
                    mma8(c[1][nt], a[cur][1][0], a[cur][1][1], a[cur][1][2], a[cur][1][3], bv.x, bv.y);
                    mma8(c[1][nt], a[cur][1][4], a[cur][1][5], a[cur][1][6], a[cur][1][7], bv.z, bv.w);
                }
            }
        }

        // ---- epilogue: bias + LN(quad shuffles) + PReLU + store ----
        #pragma unroll
        for (int mt = 0; mt < 2; mt++) {
            #pragma unroll
            for (int rh = 0; rh < 2; rh++) {
                int r = R0 + mt * 16 + g + 8 * rh;
                float s = 0.f;
                #pragma unroll
                for (int nt = 0; nt < 16; nt++) {
                    int col = nt * 8 + 2 * t;
                    c[mt][nt][2*rh]   += sBias[col];
                    c[mt][nt][2*rh+1] += sBias[col + 1];
                    s += c[mt][nt][2*rh] + c[mt][nt][2*rh+1];
                }
                s += __shfl_xor_sync(0xffffffffu, s, 1);
                s += __shfl_xor_sync(0xffffffffu, s, 2);
                float mu = s * 0.0078125f;
                float q = 0.f;
                #pragma unroll
                for (int nt = 0; nt < 16; nt++) {
                    c[mt][nt][2*rh]   -= mu;
                    c[mt][nt][2*rh+1] -= mu;
                    q = fmaf(c[mt][nt][2*rh],   c[mt][nt][2*rh],
                        fmaf(c[mt][nt][2*rh+1], c[mt][nt][2*rh+1], q));
                }
                q += __shfl_xor_sync(0xffffffffu, q, 1);
                q += __shfl_xor_sync(0xffffffffu, q, 2);
                float rstd = rsqrtf(q * 0.0078125f + 1e-5f);
                if (r < N) {
                    #pragma unroll
                    for (int nt = 0; nt < 16; nt++) {
                        int col = nt * 8 + 2 * t;
                        float y0 = c[mt][nt][2*rh]   * rstd * sG[col]     + sB2[col];
                        float y1 = c[mt][nt][2*rh+1] * rstd * sG[col + 1] + sB2[col + 1];
                        y0 = y0 >= 0.f ? y0 : al * y0;
                        y1 = y1 >= 0.f ? y1 : al * y1;
                        *reinterpret_cast<float2*>(hout + (size_t)r * 128 + col) =
                            make_float2(y0, y1);
                    }
                }
            }
        }
    }
}

// ======================= Classifier (FFMA2, proven) ========================
__global__ __launch_bounds__(256, 2)
void classifier_kernel(const float* __restrict__ hin,
                       const float* __restrict__ W1,
                       const float* __restrict__ b1,
                       const float* __restrict__ lng,
                       const float* __restrict__ lnb,
                       const float* __restrict__ W2,
                       const float* __restrict__ b2,
                       float*       __restrict__ out,
                       int N) {
    extern __shared__ float smemf[];
    float4* sW4 = reinterpret_cast<float4*>(smemf);
    U64*    sP  = reinterpret_cast<U64*>(smemf + 16384);

    int tid = threadIdx.x, lane = tid & 31, warp = tid >> 5;

    const float4* W14 = reinterpret_cast<const float4*>(W1);
    #pragma unroll
    for (int i = tid; i < 4096; i += 256) sW4[i] = W14[i];
    __syncthreads();

    float4 b1v = *reinterpret_cast<const float4*>(b1  + lane * 4);
    float4 gg  = *reinterpret_cast<const float4*>(lng + lane * 4);
    float4 bb  = *reinterpret_cast<const float4*>(lnb + lane * 4);
    float gA[4] = {gg.x, gg.y, gg.z, gg.w};
    float bA[4] = {bb.x, bb.y, bb.z, bb.w};
    U64 bp[4] = {pk2(b1v.x, b1v.x), pk2(b1v.y, b1v.y),
                 pk2(b1v.z, b1v.z), pk2(b1v.w, b1v.w)};
    const U64 NEG1   = pk2(-1.f, -1.f);
    const U64 INV128 = pk2(0.0078125f, 0.0078125f);

    float w2c0[4], w2c1[4];
    #pragma unroll
    for (int c = 0; c < 4; c++) {
        w2c0[c] = __ldg(W2 + (lane * 4 + c) * 2 + 0);
        w2c1[c] = __ldg(W2 + (lane * 4 + c) * 2 + 1);
    }
    float b20 = __ldg(b2 + 0), b21 = __ldg(b2 + 1);

    U64* sw = sP + warp * 512;
    int gw = blockIdx.x * 8 + warp;
    int stride = gridDim.x * 8 * 8;

    for (int base = gw * 8; base < N; base += stride) {
        __syncwarp();
        #pragma unroll
        for (int p = 0; p < 4; p++) {
            int r0 = base + 2 * p, r1 = r0 + 1;
            float4 x0 = {0,0,0,0}, x1 = {0,0,0,0};
            if (r0 < N) x0 = *reinterpret_cast<const float4*>(hin + (size_t)r0 * DD + lane * 4);
            if (r1 < N) x1 = *reinterpret_cast<const float4*>(hin + (size_t)r1 * DD + lane * 4);
            float2* dx = reinterpret_cast<float2*>(sw + p * 128);
            dx[lane * 4 + 0] = make_float2(x0.x, x1.x);
            dx[lane * 4 + 1] = make_float2(x0.y, x1.y);
            dx[lane * 4 + 2] = make_float2(x0.z, x1.z);
            dx[lane * 4 + 3] = make_float2(x0.w, x1.w);
        }
        __syncwarp();

        U64 acc[4][4];
        #pragma unroll
        for (int p = 0; p < 4; p++)
            #pragma unroll
            for (int c = 0; c < 4; c++) acc[p][c] = bp[c];

        #pragma unroll 4
        for (int k = 0; k < 128; k += 2) {
            float4 w0 = sW4[k * 32 + lane], w1 = sW4[k * 32 + 32 + lane];
            U64 w0p[4] = {pk2(w0.x,w0.x), pk2(w0.y,w0.y), pk2(w0.z,w0.z), pk2(w0.w,w0.w)};
            U64 w1p[4] = {pk2(w1.x,w1.x), pk2(w1.y,w1.y), pk2(w1.z,w1.z), pk2(w1.w,w1.w)};
            #pragma unroll
            for (int p = 0; p < 4; p++) {
                ulonglong2 xp = *reinterpret_cast<const ulonglong2*>(sw + p * 128 + k);
                #pragma unroll
                for (int c = 0; c < 4; c++) {
                    acc[p][c] = f2(xp.x, w0p[c], acc[p][c]);
                    acc[p][c] = f2(xp.y, w1p[c], acc[p][c]);
                }
            }
        }

        #pragma unroll
        for (int p = 0; p < 4; p++) {
            #pragma unroll
            for (int c = 0; c < 4; c++) {
                float lo, hi; upk2(acc[p][c], lo, hi);
                acc[p][c] = pk2(fmaxf(lo, 0.f), fmaxf(hi, 0.f));
            }
            U64 s = add2(add2(acc[p][0], acc[p][1]), add2(acc[p][2], acc[p][3]));
            #pragma unroll
            for (int o = 16; o; o >>= 1) s = add2(s, shfl64(s, o));
            U64 mu = mul2(s, INV128);
            U64 d[4];
            #pragma unroll
            for (int c = 0; c < 4; c++) d[c] = f2(mu, NEG1, acc[p][c]);
            U64 q = add2(add2(mul2(d[0], d[0]), mul2(d[1], d[1])),
                         add2(mul2(d[2], d[2]), mul2(d[3], d[3])));
            #pragma unroll
            for (int o = 16; o; o >>= 1) q = add2(q, shfl64(q, o));
            float ql, qh; upk2(q, ql, qh);
            float rl = rsqrtf(ql * 0.0078125f + 1e-5f);
            float rh = rsqrtf(qh * 0.0078125f + 1e-5f);

            float p0lo = 0.f, p1lo = 0.f, p0hi = 0.f, p1hi = 0.f;
            #pragma unroll
            for (int c = 0; c < 4; c++) {
                float dl, dh2; upk2(d[c], dl, dh2);
                float zl = dl * rl * gA[c] + bA[c];
                float zh = dh2 * rh * gA[c] + bA[c];
                p0lo += zl * w2c0[c]; p1lo += zl * w2c1[c];
                p0hi += zh * w2c0[c]; p1hi += zh * w2c1[c];
            }
            U64 P0 = pk2(p0lo, p0hi), P1 = pk2(p1lo, p1hi);
            #pragma unroll
            for (int o = 16; o; o >>= 1) {
                P0 = add2(P0, shfl64(P0, o));
                P1 = add2(P1, shfl64(P1, o));
            }
            if (lane == 0) {
                float a0, a1, c0, c1;
                upk2(P0, a0, a1); upk2(P1, c0, c1);
                int r0 = base + 2 * p, r1 = r0 + 1;
                if (r0 < N) { out[(size_t)r0 * 2 + 0] = a0 + b20; out[(size_t)r0 * 2 + 1] = c0 + b21; }
                if (r1 < N) { out[(size_t)r1 * 2 + 0] = a1 + b20; out[(size_t)r1 * 2 + 1] = c1 + b21; }
            }
        }
    }
}

// ---------------------------------------------------------------------------
extern "C" void kernel_launch(void* const* d_in, const int* in_sizes, int n_in,
                              void* d_out, int out_size) {
    const float* features = (const float*)d_in[0];
    const int*   ei       = (const int*)  d_in[1];
    const float* ew       = (const float*)d_in[2];
    const float* Wrel     = (const float*)d_in[3];
    const float* Wroot    = (const float*)d_in[4];
    const float* bias     = (const float*)d_in[5];
    const float* lng      = (const float*)d_in[6];
    const float* lnb      = (const float*)d_in[7];
    const float* alpha    = (const float*)d_in[8];
    const float* W1       = (const float*)d_in[9];
    const float* b1       = (const float*)d_in[10];
    const float* cg       = (const float*)d_in[11];
    const float* cb       = (const float*)d_in[12];
    const float* W2       = (const float*)d_in[13];
    const float* b2       = (const float*)d_in[14];

    int N = in_sizes[0] / DD;
    int E = in_sizes[1] / 2;
    int L = in_sizes[8];

    float *buf0, *buf1, *agg, *ewt;
    int *cnt, *off, *bsum, *esrc;
    cudaGetSymbolAddress((void**)&buf0, g_buf0);
    cudaGetSymbolAddress((void**)&buf1, g_buf1);
    cudaGetSymbolAddress((void**)&agg,  g_agg);
    cudaGetSymbolAddress((void**)&cnt,  g_cnt);
    cudaGetSymbolAddress((void**)&off,  g_off);
    cudaGetSymbolAddress((void**)&bsum, g_bsum);
    cudaGetSymbolAddress((void**)&esrc, g_esrc);
    cudaGetSymbolAddress((void**)&ewt,  g_ewt);

    int sm = 148;
    cudaDeviceGetAttribute(&sm, cudaDevAttrMultiProcessorCount, 0);

    size_t smemL = 131072;  // 2 x 64 KB B fragments
    size_t smemC = 98304;
    cudaFuncSetAttribute(layer_mma_kernel,  cudaFuncAttributeMaxDynamicSharedMemorySize, (int)smemL);
    cudaFuncSetAttribute(classifier_kernel, cudaFuncAttributeMaxDynamicSharedMemorySize, (int)smemC);

    // ---- CSR build: 5 launches, no memsets (cnt self-restores to zero) ----
    int NB = (N + 1023) / 1024;
    hist_kernel <<<(E + 255) / 256, 256>>>(ei, cnt, E);
    scan1_kernel<<<NB, 1024>>>(cnt, off, bsum, N);
    scan2_kernel<<<1, 128>>>(bsum, off, NB, N);
    place_kernel<<<(E + 255) / 256, 256>>>(ei, ew, off, bsum, cnt, esrc, ewt, E);

    int gatherBlocks = (N + 7) / 8;

    const float* hin = features;
    float* pong[2] = { buf0, buf1 };
    for (int i = 0; i < L; i++) {
        float* hout = pong[i & 1];
        gather_kernel<<<gatherBlocks, 256>>>(hin, off, bsum, esrc, ewt, agg, N);
        layer_mma_kernel<<<sm, 256, smemL>>>(hin, agg,
                                             Wrel  + (size_t)i * DD * DD,
                                             Wroot + (size_t)i * DD * DD,
                                             bias + i * DD, lng + i * DD, lnb + i * DD,
                                             alpha + i, hout, N);
        hin = hout;
    }
    classifier_kernel<<<2 * sm, 256, smemC>>>(hin, W1, b1, cg, cb, W2, b2,
                                              (float*)d_out, N);
}

// round 8
// speedup vs baseline: 2.1322x; 1.0724x over previous
#include <cuda_runtime.h>
#include <cuda_fp16.h>
#include <cstdint>

// ---------------------------------------------------------------------------
// GNN: L x { agg = scatter_add(h[src]*ew, dst); h = PReLU(LN(agg@Wrel + h@Wroot + b)) }
// then logits = LN(relu(h@W1+b1)) @ W2 + b2
// R8: fp16 mirror of h for the gather (halves L2 gather traffic; fp16 mantissa
//     == tf32 mantissa so added error ~ existing tf32 error), classifier on
//     tf32 mma. Layer GEMM structure from R7 (A direct-from-global).
// ---------------------------------------------------------------------------

#define MAXN 100000
#define MAXE 1600000
#define DD   128
typedef unsigned long long U64;

__device__ float  g_buf0[MAXN * DD];
__device__ float  g_buf1[MAXN * DD];
__device__ float  g_agg [MAXN * DD];
__device__ __half g_h16 [MAXN * DD];
__device__ int    g_cnt [MAXN];       // zero at entry of every call (see place)
__device__ int    g_off [MAXN + 1];
__device__ int    g_bsum[128];
__device__ int    g_esrc[MAXE];
__device__ float  g_ewt [MAXE];

__device__ __forceinline__ uint32_t tf32c(float f) {
    uint32_t r; asm("cvt.rna.tf32.f32 %0, %1;" : "=r"(r) : "f"(f)); return r;
}
__device__ __forceinline__ void mma8(float c[4], uint32_t a0, uint32_t a1,
                                     uint32_t a2, uint32_t a3,
                                     uint32_t b0, uint32_t b1) {
    asm volatile(
        "mma.sync.aligned.m16n8k8.row.col.f32.tf32.tf32.f32 "
        "{%0,%1,%2,%3},{%4,%5,%6,%7},{%8,%9},{%0,%1,%2,%3};"
        : "+f"(c[0]), "+f"(c[1]), "+f"(c[2]), "+f"(c[3])
        : "r"(a0), "r"(a1), "r"(a2), "r"(a3), "r"(b0), "r"(b1));
}

// ======================= CSR build (no memsets) ============================
__global__ void hist_kernel(const int* __restrict__ ei, int* __restrict__ cnt, int E) {
    int e = blockIdx.x * blockDim.x + threadIdx.x;
    if (e < E) atomicAdd(cnt + __ldg(ei + E + e), 1);
}
__global__ void scan1_kernel(const int* __restrict__ cnt, int* __restrict__ off,
                             int* __restrict__ bsum, int N) {
    __shared__ int s[1024];
    int tid = threadIdx.x;
    int i = blockIdx.x * 1024 + tid;
    int v = (i < N) ? cnt[i] : 0;
    s[tid] = v; __syncthreads();
    #pragma unroll
    for (int d = 1; d < 1024; d <<= 1) {
        int t = (tid >= d) ? s[tid - d] : 0;
        __syncthreads();
        s[tid] += t;
        __syncthreads();
    }
    if (i < N) off[i] = s[tid] - v;
    if (tid == 1023) bsum[blockIdx.x] = s[1023];
}
__global__ void scan2_kernel(int* __restrict__ bsum, int* __restrict__ off,
                             int NB, int N) {
    __shared__ int s[128];
    int tid = threadIdx.x;
    int v = (tid < NB) ? bsum[tid] : 0;
    s[tid] = v; __syncthreads();
    #pragma unroll
    for (int d = 1; d < 128; d <<= 1) {
        int t = (tid >= d) ? s[tid - d] : 0;
        __syncthreads();
        s[tid] += t;
        __syncthreads();
    }
    if (tid < NB) bsum[tid] = s[tid] - v;
    if (tid == 127) off[N] = s[127];
}
__global__ void place_kernel(const int* __restrict__ ei, const float* __restrict__ ew,
                             const int* __restrict__ off, const int* __restrict__ bsum,
                             int* __restrict__ cursor,
                             int* __restrict__ esrc, float* __restrict__ ewt, int E) {
    int e = blockIdx.x * blockDim.x + threadIdx.x;
    if (e >= E) return;
    int src = __ldg(ei + e);
    int dst = __ldg(ei + E + e);
    int pos = off[dst] + bsum[dst >> 10] + (atomicSub(cursor + dst, 1) - 1);
    esrc[pos] = src;
    ewt[pos]  = __ldg(ew + e);
}

// ======================= fp32 -> fp16 convert ==============================
__global__ void to_half_kernel(const float4* __restrict__ x,
                               uint2* __restrict__ y, int n4) {
    int i = blockIdx.x * blockDim.x + threadIdx.x;
    if (i >= n4) return;
    float4 v = x[i];
    __half2 a = __floats2half2_rn(v.x, v.y);
    __half2 b = __floats2half2_rn(v.z, v.w);
    y[i] = make_uint2(*(uint32_t*)&a, *(uint32_t*)&b);
}

// ======================= Aggregation: warp per node (fp16 reads) ===========
__global__ __launch_bounds__(256)
void gather_kernel(const __half* __restrict__ h16,
                   const int*    __restrict__ off,
                   const int*    __restrict__ bsum,
                   const int*    __restrict__ esrc,
                   const float*  __restrict__ ewt,
                   float*        __restrict__ agg, int N) {
    int warp = threadIdx.x >> 5, lane = threadIdx.x & 31;
    int node = blockIdx.x * 8 + warp;
    if (node >= N) return;
    int beg = __ldg(off + node) + __ldg(bsum + (node >> 10));
    int end = (node + 1 == N) ? __ldg(off + N)
                              : __ldg(off + node + 1) + __ldg(bsum + ((node + 1) >> 10));
    float4 acc = {0.f, 0.f, 0.f, 0.f};
    int e = beg;
    for (; e + 1 < end; e += 2) {
        int   s0 = __ldg(esrc + e),  s1 = __ldg(esrc + e + 1);
        float w0 = __ldg(ewt + e),   w1 = __ldg(ewt + e + 1);
        uint2 r0 = *reinterpret_cast<const uint2*>(h16 + (size_t)s0 * DD + lane * 4);
        uint2 r1 = *reinterpret_cast<const uint2*>(h16 + (size_t)s1 * DD + lane * 4);
        float2 a0 = __half22float2(*(__half2*)&r0.x);
        float2 b0 = __half22float2(*(__half2*)&r0.y);
        float2 a1 = __half22float2(*(__half2*)&r1.x);
        float2 b1 = __half22float2(*(__half2*)&r1.y);
        acc.x = fmaf(w0, a0.x, fmaf(w1, a1.x, acc.x));
        acc.y = fmaf(w0, a0.y, fmaf(w1, a1.y, acc.y));
        acc.z = fmaf(w0, b0.x, fmaf(w1, b1.x, acc.z));
        acc.w = fmaf(w0, b0.y, fmaf(w1, b1.y, acc.w));
    }
    if (e < end) {
        int   s0 = __ldg(esrc + e);
        float w0 = __ldg(ewt + e);
        uint2 r0 = *reinterpret_cast<const uint2*>(h16 + (size_t)s0 * DD + lane * 4);
        float2 a0 = __half22float2(*(__half2*)&r0.x);
        float2 b0 = __half22float2(*(__half2*)&r0.y);
        acc.x = fmaf(w0, a0.x, acc.x);
        acc.y = fmaf(w0, a0.y, acc.y);
        acc.z = fmaf(w0, b0.x, acc.z);
        acc.w = fmaf(w0, b0.y, acc.w);
    }
    *reinterpret_cast<float4*>(agg + (size_t)node * DD + lane * 4) = acc;
}

// ============== Layer GEMM via warp-level mma.sync tf32 (R7 core) ==========
__global__ __launch_bounds__(256, 1)
void layer_mma_kernel(const float* __restrict__ hin,
                      const float* __restrict__ agg,
                      const float* __restrict__ Wrel,
                      const float* __restrict__ Wroot,
                      const float* __restrict__ bias,
                      const float* __restrict__ lng,
                      const float* __restrict__ lnb,
                      const float* __restrict__ alpha,
                      float*       __restrict__ hout,
                      __half*      __restrict__ hout16,
                      int N) {
    extern __shared__ uint32_t smemu[];
    uint32_t* sBr = smemu;            // 64 KB Wrel fragments
    uint32_t* sBo = smemu + 16384;    // 64 KB Wroot fragments
    __shared__ float sBias[128], sG[128], sB2[128];

    int tid = threadIdx.x, wid = tid >> 5, lane = tid & 31;
    int g = lane >> 2, t = lane & 3;

    for (int idx = tid; idx < 4096; idx += 256) {
        int k = idx >> 5, n4 = (idx & 31) * 4;
        float4 vr = *reinterpret_cast<const float4*>(Wrel  + (size_t)k * 128 + n4);
        float4 vo = *reinterpret_cast<const float4*>(Wroot + (size_t)k * 128 + n4);
        int kk = k >> 3, t8 = k & 7, breg = t8 >> 2, tt = t8 & 3;
        int j = ((kk & 1) << 1) + breg, kkp = kk >> 1;
        float vrA[4] = {vr.x, vr.y, vr.z, vr.w};
        float voA[4] = {vo.x, vo.y, vo.z, vo.w};
        #pragma unroll
        for (int m = 0; m < 4; m++) {
            int n = n4 + m, nt = n >> 3, gg = n & 7;
            int base = ((nt * 8 + kkp) * 32 + gg * 4 + tt) * 4 + j;
            sBr[base] = tf32c(vrA[m]);
            sBo[base] = tf32c(voA[m]);
        }
    }
    if (tid < 128) {
        sBias[tid] = __ldg(bias + tid);
        sG[tid]    = __ldg(lng + tid);
        sB2[tid]   = __ldg(lnb + tid);
    }
    __syncthreads();

    float al = __ldg(alpha);
    int numUnits = (N + 31) >> 5;
    int ustride  = gridDim.x * 8;

    for (int unit = blockIdx.x * 8 + wid; unit < numUnits; unit += ustride) {
        int R0 = unit * 32;
        float c[2][16][4];
        #pragma unroll
        for (int mt = 0; mt < 2; mt++)
            #pragma unroll
            for (int nt = 0; nt < 16; nt++)
                #pragma unroll
                for (int j = 0; j < 4; j++) c[mt][nt][j] = 0.f;

        #pragma unroll
        for (int half = 0; half < 2; half++) {
            const float*    src = half ? hin : agg;
            const uint32_t* sBf = half ? sBo : sBr;

            const float* rp[2][2];
            bool rv[2][2];
            #pragma unroll
            for (int mt = 0; mt < 2; mt++)
                #pragma unroll
                for (int rh = 0; rh < 2; rh++) {
                    int r = R0 + mt * 16 + g + 8 * rh;
                    rv[mt][rh] = r < N;
                    rp[mt][rh] = src + (size_t)r * 128 + t;
                }

            uint32_t a[2][2][8];
            #pragma unroll
            for (int mt = 0; mt < 2; mt++) {
                #pragma unroll
                for (int q = 0; q < 2; q++) {
                    int o = q * 8;
                    a[0][mt][q*4+0] = tf32c(rv[mt][0] ? rp[mt][0][o]     : 0.f);
                    a[0][mt][q*4+1] = tf32c(rv[mt][1] ? rp[mt][1][o]     : 0.f);
                    a[0][mt][q*4+2] = tf32c(rv[mt][0] ? rp[mt][0][o + 4] : 0.f);
                    a[0][mt][q*4+3] = tf32c(rv[mt][1] ? rp[mt][1][o + 4] : 0.f);
                }
            }

            #pragma unroll
            for (int kkp = 0; kkp < 8; kkp++) {
                int cur = kkp & 1;
                if (kkp < 7) {
                    int kb = (kkp + 1) * 16;
                    #pragma unroll
                    for (int mt = 0; mt < 2; mt++) {
                        #pragma unroll
                        for (int q = 0; q < 2; q++) {
                            int o = kb + q * 8;
                            a[cur^1][mt][q*4+0] = tf32c(rv[mt][0] ? rp[mt][0][o]     : 0.f);
                            a[cur^1][mt][q*4+1] = tf32c(rv[mt][1] ? rp[mt][1][o]     : 0.f);
                            a[cur^1][mt][q*4+2] = tf32c(rv[mt][0] ? rp[mt][0][o + 4] : 0.f);
                            a[cur^1][mt][q*4+3] = tf32c(rv[mt][1] ? rp[mt][1][o + 4] : 0.f);
                        }
                    }
                }
                #pragma unroll
                for (int nt = 0; nt < 16; nt++) {
                    uint4 bv = *reinterpret_cast<const uint4*>(
                        sBf + ((nt * 8 + kkp) * 32 + lane) * 4);
                    mma8(c[0][nt], a[cur][0][0], a[cur][0][1], a[cur][0][2], a[cur][0][3], bv.x, bv.y);
                    mma8(c[0][nt], a[cur][0][4], a[cur][0][5], a[cur][0][6], a[cur][0][7], bv.z, bv.w);
                    mma8(c[1][nt], a[cur][1][0], a[cur][1][1], a[cur][1][2], a[cur][1][3], bv.x, bv.y);
                    mma8(c[1][nt], a[cur][1][4], a[cur][1][5], a[cur][1][6], a[cur][1][7], bv.z, bv.w);
                }
            }
        }

        // ---- epilogue: bias + LN + PReLU + fp32/fp16 store ----
        #pragma unroll
        for (int mt = 0; mt < 2; mt++) {
            #pragma unroll
            for (int rh = 0; rh < 2; rh++) {
                int r = R0 + mt * 16 + g + 8 * rh;
                float s = 0.f;
                #pragma unroll
                for (int nt = 0; nt < 16; nt++) {
                    int col = nt * 8 + 2 * t;
                    c[mt][nt][2*rh]   += sBias[col];
                    c[mt][nt][2*rh+1] += sBias[col + 1];
                    s += c[mt][nt][2*rh] + c[mt][nt][2*rh+1];
                }
                s += __shfl_xor_sync(0xffffffffu, s, 1);
                s += __shfl_xor_sync(0xffffffffu, s, 2);
                float mu = s * 0.0078125f;
                float q = 0.f;
                #pragma unroll
                for (int nt = 0; nt < 16; nt++) {
                    c[mt][nt][2*rh]   -= mu;
                    c[mt][nt][2*rh+1] -= mu;
                    q = fmaf(c[mt][nt][2*rh],   c[mt][nt][2*rh],
                        fmaf(c[mt][nt][2*rh+1], c[mt][nt][2*rh+1], q));
                }
                q += __shfl_xor_sync(0xffffffffu, q, 1);
                q += __shfl_xor_sync(0xffffffffu, q, 2);
                float rstd = rsqrtf(q * 0.0078125f + 1e-5f);
                if (r < N) {
                    #pragma unroll
                    for (int nt = 0; nt < 16; nt++) {
                        int col = nt * 8 + 2 * t;
                        float y0 = c[mt][nt][2*rh]   * rstd * sG[col]     + sB2[col];
                        float y1 = c[mt][nt][2*rh+1] * rstd * sG[col + 1] + sB2[col + 1];
                        y0 = y0 >= 0.f ? y0 : al * y0;
                        y1 = y1 >= 0.f ? y1 : al * y1;
                        *reinterpret_cast<float2*>(hout + (size_t)r * 128 + col) =
                            make_float2(y0, y1);
                        *reinterpret_cast<__half2*>(hout16 + (size_t)r * 128 + col) =
                            __floats2half2_rn(y0, y1);
                    }
                }
            }
        }
    }
}

// ============== Classifier via warp-level mma.sync tf32 ====================
// logits = LN(relu(h@W1+b1)) @ W2 + b2. Same warp unit (32 rows x 128 cols);
// epilogue does ReLU + LN + the 128->2 projection with quad shuffles.
__global__ __launch_bounds__(256, 1)
void cls_mma_kernel(const float* __restrict__ hin,
                    const float* __restrict__ W1,
                    const float* __restrict__ b1,
                    const float* __restrict__ lng,
                    const float* __restrict__ lnb,
                    const float* __restrict__ W2,
                    const float* __restrict__ b2,
                    float*       __restrict__ out,
                    int N) {
    extern __shared__ uint32_t smemu[];
    uint32_t* sBf = smemu;            // 64 KB W1 fragments
    __shared__ float sBias[128], sG[128], sB2[128], sW2[256];

    int tid = threadIdx.x, wid = tid >> 5, lane = tid & 31;
    int g = lane >> 2, t = lane & 3;

    for (int idx = tid; idx < 4096; idx += 256) {
        int k = idx >> 5, n4 = (idx & 31) * 4;
        float4 vw = *reinterpret_cast<const float4*>(W1 + (size_t)k * 128 + n4);
        int kk = k >> 3, t8 = k & 7, breg = t8 >> 2, tt = t8 & 3;
        int j = ((kk & 1) << 1) + breg, kkp = kk >> 1;
        float vA[4] = {vw.x, vw.y, vw.z, vw.w};
        #pragma unroll
        for (int m = 0; m < 4; m++) {
            int n = n4 + m, nt = n >> 3, gg = n & 7;
            sBf[((nt * 8 + kkp) * 32 + gg * 4 + tt) * 4 + j] = tf32c(vA[m]);
        }
    }
    if (tid < 128) {
        sBias[tid] = __ldg(b1 + tid);
        sG[tid]    = __ldg(lng + tid);
        sB2[tid]   = __ldg(lnb + tid);
        sW2[tid * 2]     = __ldg(W2 + tid * 2);
        sW2[tid * 2 + 1] = __ldg(W2 + tid * 2 + 1);
    }
    __syncthreads();

    float b20 = __ldg(b2 + 0), b21 = __ldg(b2 + 1);
    int numUnits = (N + 31) >> 5;
    int ustride  = gridDim.x * 8;

    for (int unit = blockIdx.x * 8 + wid; unit < numUnits; unit += ustride) {
        int R0 = unit * 32;
        float c[2][16][4];
        #pragma unroll
        for (int mt = 0; mt < 2; mt++)
            #pragma unroll
            for (int nt = 0; nt < 16; nt++)
                #pragma unroll
                for (int j = 0; j < 4; j++) c[mt][nt][j] = 0.f;

        const float* rp[2][2];
        bool rv[2][2];
        #pragma unroll
        for (int mt = 0; mt < 2; mt++)
            #pragma unroll
            for (int rh = 0; rh < 2; rh++) {
                int r = R0 + mt * 16 + g + 8 * rh;
                rv[mt][rh] = r < N;
                rp[mt][rh] = hin + (size_t)r * 128 + t;
            }

        uint32_t a[2][2][8];
        #pragma unroll
        for (int mt = 0; mt < 2; mt++) {
            #pragma unroll
            for (int q = 0; q < 2; q++) {
                int o = q * 8;
                a[0][mt][q*4+0] = tf32c(rv[mt][0] ? rp[mt][0][o]     : 0.f);
                a[0][mt][q*4+1] = tf32c(rv[mt][1] ? rp[mt][1][o]     : 0.f);
                a[0][mt][q*4+2] = tf32c(rv[mt][0] ? rp[mt][0][o + 4] : 0.f);
                a[0][mt][q*4+3] = tf32c(rv[mt][1] ? rp[mt][1][o + 4] : 0.f);
            }
        }

        #pragma unroll
        for (int kkp = 0; kkp < 8; kkp++) {
            int cur = kkp & 1;
            if (kkp < 7) {
                int kb = (kkp + 1) * 16;
                #pragma unroll
                for (int mt = 0; mt < 2; mt++) {
                    #pragma unroll
                    for (int q = 0; q < 2; q++) {
                        int o = kb + q * 8;
                        a[cur^1][mt][q*4+0] = tf32c(rv[mt][0] ? rp[mt][0][o]     : 0.f);
                        a[cur^1][mt][q*4+1] = tf32c(rv[mt][1] ? rp[mt][1][o]     : 0.f);
                        a[cur^1][mt][q*4+2] = tf32c(rv[mt][0] ? rp[mt][0][o + 4] : 0.f);
                        a[cur^1][mt][q*4+3] = tf32c(rv[mt][1] ? rp[mt][1][o + 4] : 0.f);
                    }
                }
            }
            #pragma unroll
            for (int nt = 0; nt < 16; nt++) {
                uint4 bv = *reinterpret_cast<const uint4*>(
                    sBf + ((nt * 8 + kkp) * 32 + lane) * 4);
                mma8(c[0][nt], a[cur][0][0], a[cur][0][1], a[cur][0][2], a[cur][0][3], bv.x, bv.y);
                mma8(c[0][nt], a[cur][0][4], a[cur][0][5], a[cur][0][6], a[cur][0][7], bv.z, bv.w);
                mma8(c[1][nt], a[cur][1][0], a[cur][1][1], a[cur][1][2], a[cur][1][3], bv.x, bv.y);
                mma8(c[1][nt], a[cur][1][4], a[cur][1][5], a[cur][1][6], a[cur][1][7], bv.z, bv.w);
            }
        }

        // ---- epilogue: bias + ReLU + LN + W2 projection ----
        #pragma unroll
        for (int mt = 0; mt < 2; mt++) {
            #pragma unroll
            for (int rh = 0; rh < 2; rh++) {
                int r = R0 + mt * 16 + g + 8 * rh;
                float s = 0.f;
                #pragma unroll
                for (int nt = 0; nt < 16; nt++) {
                    int col = nt * 8 + 2 * t;
                    float v0 = fmaxf(c[mt][nt][2*rh]   + sBias[col],     0.f);
                    float v1 = fmaxf(c[mt][nt][2*rh+1] + sBias[col + 1], 0.f);
                    c[mt][nt][2*rh]   = v0;
                    c[mt][nt][2*rh+1] = v1;
                    s += v0 + v1;
                }
                s += __shfl_xor_sync(0xffffffffu, s, 1);
                s += __shfl_xor_sync(0xffffffffu, s, 2);
                float mu = s * 0.0078125f;
                float q = 0.f;
                #pragma unroll
                for (int nt = 0; nt < 16; nt++) {
                    c[mt][nt][2*rh]   -= mu;
                    c[mt][nt][2*rh+1] -= mu;
                    q = fmaf(c[mt][nt][2*rh],   c[mt][nt][2*rh],
                        fmaf(c[mt][nt][2*rh+1], c[mt][nt][2*rh+1], q));
                }
                q += __shfl_xor_sync(0xffffffffu, q, 1);
                q += __shfl_xor_sync(0xffffffffu, q, 2);
                float rstd = rsqrtf(q * 0.0078125f + 1e-5f);
                float p0 = 0.f, p1 = 0.f;
                #pragma unroll
                for (int nt = 0; nt < 16; nt++) {
                    int col = nt * 8 + 2 * t;
                    float z0 = c[mt][nt][2*rh]   * rstd * sG[col]     + sB2[col];
                    float z1 = c[mt][nt][2*rh+1] * rstd * sG[col + 1] + sB2[col + 1];
                    p0 = fmaf(z0, sW2[col * 2],       fmaf(z1, sW2[(col + 1) * 2],     p0));
                    p1 = fmaf(z0, sW2[col * 2 + 1],   fmaf(z1, sW2[(col + 1) * 2 + 1], p1));
                }
                p0 += __shfl_xor_sync(0xffffffffu, p0, 1);
                p0 += __shfl_xor_sync(0xffffffffu, p0, 2);
                p1 += __shfl_xor_sync(0xffffffffu, p1, 1);
                p1 += __shfl_xor_sync(0xffffffffu, p1, 2);
                if (t == 0 && r < N) {
                    out[(size_t)r * 2 + 0] = p0 + b20;
                    out[(size_t)r * 2 + 1] = p1 + b21;
                }
            }
        }
    }
}

// ---------------------------------------------------------------------------
extern "C" void kernel_launch(void* const* d_in, const int* in_sizes, int n_in,
                              void* d_out, int out_size) {
    const float* features = (const float*)d_in[0];
    const int*   ei       = (const int*)  d_in[1];
    const float* ew       = (const float*)d_in[2];
    const float* Wrel     = (const float*)d_in[3];
    const float* Wroot    = (const float*)d_in[4];
    const float* bias     = (const float*)d_in[5];
    const float* lng      = (const float*)d_in[6];
    const float* lnb      = (const float*)d_in[7];
    const float* alpha    = (const float*)d_in[8];
    const float* W1       = (const float*)d_in[9];
    const float* b1       = (const float*)d_in[10];
    const float* cg       = (const float*)d_in[11];
    const float* cb       = (const float*)d_in[12];
    const float* W2       = (const float*)d_in[13];
    const float* b2       = (const float*)d_in[14];

    int N = in_sizes[0] / DD;
    int E = in_sizes[1] / 2;
    int L = in_sizes[8];

    float *buf0, *buf1, *agg, *ewt;
    __half *h16;
    int *cnt, *off, *bsum, *esrc;
    cudaGetSymbolAddress((void**)&buf0, g_buf0);
    cudaGetSymbolAddress((void**)&buf1, g_buf1);
    cudaGetSymbolAddress((void**)&agg,  g_agg);
    cudaGetSymbolAddress((void**)&h16,  g_h16);
    cudaGetSymbolAddress((void**)&cnt,  g_cnt);
    cudaGetSymbolAddress((void**)&off,  g_off);
    cudaGetSymbolAddress((void**)&bsum, g_bsum);
    cudaGetSymbolAddress((void**)&esrc, g_esrc);
    cudaGetSymbolAddress((void**)&ewt,  g_ewt);

    int sm = 148;
    cudaDeviceGetAttribute(&sm, cudaDevAttrMultiProcessorCount, 0);

    size_t smemL = 131072;  // 2 x 64 KB
    size_t smemC = 65536;   // 64 KB
    cudaFuncSetAttribute(layer_mma_kernel, cudaFuncAttributeMaxDynamicSharedMemorySize, (int)smemL);
    cudaFuncSetAttribute(cls_mma_kernel,   cudaFuncAttributeMaxDynamicSharedMemorySize, (int)smemC);

    // ---- CSR build (no memsets; cnt self-restores) ----
    int NB = (N + 1023) / 1024;
    hist_kernel <<<(E + 255) / 256, 256>>>(ei, cnt, E);
    scan1_kernel<<<NB, 1024>>>(cnt, off, bsum, N);
    scan2_kernel<<<1, 128>>>(bsum, off, NB, N);
    place_kernel<<<(E + 255) / 256, 256>>>(ei, ew, off, bsum, cnt, esrc, ewt, E);

    // fp16 mirror of input features
    int n4 = N * DD / 4;
    to_half_kernel<<<(n4 + 255) / 256, 256>>>((const float4*)features, (uint2*)h16, n4);

    int gatherBlocks = (N + 7) / 8;

    const float* hin = features;
    float* pong[2] = { buf0, buf1 };
    for (int i = 0; i < L; i++) {
        float* hout = pong[i & 1];
        gather_kernel<<<gatherBlocks, 256>>>(h16, off, bsum, esrc, ewt, agg, N);
        layer_mma_kernel<<<sm, 256, smemL>>>(hin, agg,
                                             Wrel  + (size_t)i * DD * DD,
                                             Wroot + (size_t)i * DD * DD,
                                             bias + i * DD, lng + i * DD, lnb + i * DD,
                                             alpha + i, hout, h16, N);
        hin = hout;
    }
    cls_mma_kernel<<<sm, 256, smemC>>>(hin, W1, b1, cg, cb, W2, b2,
                                       (float*)d_out, N);
}